// round 13
// baseline (speedup 1.0000x reference)
#include <cuda_runtime.h>
#include <cuda_fp16.h>
#include <cstdint>
#include <math.h>

// ---------------------------------------------------------------------------
// SpatialTransformer via mma.sync fp16 (HMMA).
// Round 13: batch-pipelined merged launches (scores/softmax/attnV/outproj of
// different batches share launches; tails fill each other). Outproj 1-pass.
// ---------------------------------------------------------------------------

#define B_DIM 4
#define S_DIM 2048
#define C_DIM 1024
#define M_ALL (B_DIM * S_DIM)   // 8192

__device__ float g_S[(long long)B_DIM * S_DIM * S_DIM];  // scores, 64 MB
__device__ half g_x16[M_ALL * C_DIM], g_ce16[M_ALL * C_DIM];
__device__ half g_Wq16[C_DIM * C_DIM], g_Wk16[C_DIM * C_DIM];
__device__ half g_Wv16[C_DIM * C_DIM], g_Wo16[C_DIM * C_DIM];
__device__ half g_Q16[M_ALL * C_DIM], g_K16[M_ALL * C_DIM];
__device__ half g_Vt16[C_DIM * M_ALL];                      // V^T [C][B*S]
__device__ half g_P16[(long long)B_DIM * S_DIM * S_DIM];
__device__ half g_T16[M_ALL * C_DIM];                       // x + attended (fp16)

__device__ __forceinline__ uint32_t smem_u32(const void* p) {
    uint32_t a;
    asm("{ .reg .u64 t; cvta.to.shared.u64 t, %1; cvt.u32.u64 %0, t; }"
        : "=r"(a) : "l"(p));
    return a;
}

#define LDMX4(r0, r1, r2, r3, addr) \
    asm volatile("ldmatrix.sync.aligned.m8n8.x4.shared.b16 {%0,%1,%2,%3}, [%4];" \
                 : "=r"(r0), "=r"(r1), "=r"(r2), "=r"(r3) : "r"(addr))
#define MMA16816(d, a, b) \
    asm volatile("mma.sync.aligned.m16n8k16.row.col.f32.f16.f16.f32 " \
                 "{%0,%1,%2,%3}, {%4,%5,%6,%7}, {%8,%9}, {%0,%1,%2,%3};" \
                 : "+f"((d)[0]), "+f"((d)[1]), "+f"((d)[2]), "+f"((d)[3]) \
                 : "r"((a)[0]), "r"((a)[1]), "r"((a)[2]), "r"((a)[3]), \
                   "r"((b)[0]), "r"((b)[1]))
#define CP_ASYNC16(dst, src) \
    asm volatile("cp.async.cg.shared.global [%0], [%1], 16;" \
                 :: "r"(dst), "l"(src) : "memory")
#define CP_COMMIT() asm volatile("cp.async.commit_group;" ::: "memory")

#define KT        32
#define ROW_H     40
#define TILE_H    (128 * ROW_H)          // halves (5120)
#define STAGE1_H  (2 * TILE_H)
#define SMEM1     (3 * STAGE1_H * 2)     // 61440 B

__device__ __forceinline__ uint32_t packh(half a, half b) {
    __half2 t; t.x = a; t.y = b;
    return *reinterpret_cast<uint32_t*>(&t);
}

// ---------------------------------------------------------------------------
// Fused rounding pass: all six fp32 tensors -> fp16.
// ---------------------------------------------------------------------------
__global__ __launch_bounds__(256)
void round_all(const float4* __restrict__ x,  const float4* __restrict__ ce,
               const float4* __restrict__ Wq, const float4* __restrict__ Wk,
               const float4* __restrict__ Wv, const float4* __restrict__ Wo,
               uint2* __restrict__ x16,  uint2* __restrict__ ce16,
               uint2* __restrict__ Wq16, uint2* __restrict__ Wk16,
               uint2* __restrict__ Wv16, uint2* __restrict__ Wo16)
{
    const int b = blockIdx.x;
    const float4* in; uint2* o; int lb;
    if (b < 8192)       { in = x;  o = x16;  lb = b; }
    else if (b < 16384) { in = ce; o = ce16; lb = b - 8192; }
    else if (b < 17408) { in = Wq; o = Wq16; lb = b - 16384; }
    else if (b < 18432) { in = Wk; o = Wk16; lb = b - 17408; }
    else if (b < 19456) { in = Wv; o = Wv16; lb = b - 18432; }
    else                { in = Wo; o = Wo16; lb = b - 19456; }

    const int i = lb * 256 + threadIdx.x;
    float4 v = in[i];
    o[i] = make_uint2(packh(__float2half(v.x), __float2half(v.y)),
                      packh(__float2half(v.z), __float2half(v.w)));
}

// ---------------------------------------------------------------------------
// 1-pass mainloop: acc += A@B^T. 2 smem tiles/stage, 3-stage ring.
// ---------------------------------------------------------------------------
__device__ __forceinline__ void gemm_core1(
    const half* __restrict__ Ag, const half* __restrict__ Bg,
    int ldA, int ldB, int K, char* smem_raw, float acc[4][8][4])
{
    const uint32_t sm_base = smem_u32(smem_raw);
    const int tid  = threadIdx.x;
    const int lane = tid & 31;
    const int wid  = tid >> 5;

    const int warp_m = (wid & 1) * 64;
    const int warp_n = (wid >> 1) * 64;

    const int r0 = tid >> 2;
    const int kc = (tid & 3) * 8;

    const int arow  = warp_m + (lane & 15);
    const int acolr = (lane >> 4) << 3;
    const int brow_off = ((lane >> 4) << 3) + (lane & 7);
    const int bcolr = lane & 8;

    const int NK = K >> 5;

    auto load_stage = [&](int buf, int kt) {
        const uint32_t sbase = sm_base + (uint32_t)(buf * STAGE1_H) * 2;
        const int kk = kt * KT + kc;
#pragma unroll
        for (int rr = 0; rr < 4; rr++) {
            const int row = r0 + rr * 32;
            const uint32_t so = (uint32_t)(row * ROW_H + kc) * 2;
            CP_ASYNC16(sbase + so,                          Ag + (size_t)row * ldA + kk);
            CP_ASYNC16(sbase + (uint32_t)(TILE_H * 2) + so, Bg + (size_t)row * ldB + kk);
        }
    };

    load_stage(0, 0);
    CP_COMMIT();
    load_stage(1, 1);
    CP_COMMIT();

    for (int kt = 0; kt < NK; ++kt) {
        if (kt + 2 < NK) {
            load_stage((kt + 2) % 3, kt + 2);
            CP_COMMIT();
        }
        const int rem = NK - 1 - kt;
        if (rem >= 2)      asm volatile("cp.async.wait_group 2;" ::: "memory");
        else if (rem == 1) asm volatile("cp.async.wait_group 1;" ::: "memory");
        else               asm volatile("cp.async.wait_group 0;" ::: "memory");
        __syncthreads();

        const uint32_t stg = sm_base + (uint32_t)((kt % 3) * STAGE1_H) * 2;

        uint32_t af[2][4][4];
        uint32_t bb[2][8][2];

#pragma unroll
        for (int half_ = 0; half_ < 2; ++half_) {
            const int kk = half_ * 16;
#pragma unroll
            for (int i = 0; i < 4; i++) {
                const uint32_t byt = (uint32_t)(((arow + i * 16) * ROW_H + kk + acolr) * 2);
                LDMX4(af[half_][i][0], af[half_][i][1], af[half_][i][2], af[half_][i][3],
                      stg + byt);
            }
#pragma unroll
            for (int jj = 0; jj < 8; jj += 2) {
                const uint32_t byt =
                    (uint32_t)(((warp_n + jj * 8 + brow_off) * ROW_H + kk + bcolr) * 2);
                LDMX4(bb[half_][jj][0], bb[half_][jj][1],
                      bb[half_][jj + 1][0], bb[half_][jj + 1][1],
                      stg + (uint32_t)(TILE_H * 2) + byt);
            }
        }

#pragma unroll
        for (int half_ = 0; half_ < 2; ++half_)
#pragma unroll
            for (int i = 0; i < 4; i++)
#pragma unroll
                for (int j = 0; j < 8; j++)
                    MMA16816(acc[i][j], af[half_][i], bb[half_][j]);

        __syncthreads();
    }
}

// ---------------------------------------------------------------------------
// Fused Q/K/V projection (1-pass): grid (8, 64, 3).
// ---------------------------------------------------------------------------
__global__ __launch_bounds__(128, 2)
void gemm_qkv(const half* __restrict__ x16, const half* __restrict__ ce16,
              const half* __restrict__ Wq16, const half* __restrict__ Wk16,
              const half* __restrict__ Wv16,
              const float* __restrict__ bq, const float* __restrict__ bk,
              const float* __restrict__ bv,
              half* __restrict__ Q16, half* __restrict__ K16,
              half* __restrict__ Vt16)
{
    extern __shared__ __align__(16) char smem_raw[];
    const int z  = blockIdx.z;
    const int m0 = blockIdx.y * 128;
    const int n0 = blockIdx.x * 128;

    const half *A_, *B_;
    const float* bias;
    if (z == 0)      { A_ = x16;  B_ = Wq16; bias = bq; }
    else if (z == 1) { A_ = ce16; B_ = Wk16; bias = bk; }
    else             { A_ = ce16; B_ = Wv16; bias = bv; }

    float acc[4][8][4];
#pragma unroll
    for (int i = 0; i < 4; i++)
#pragma unroll
        for (int j = 0; j < 8; j++)
#pragma unroll
            for (int c = 0; c < 4; c++) acc[i][j][c] = 0.f;

    gemm_core1(A_ + (size_t)m0 * C_DIM, B_ + (size_t)n0 * C_DIM,
               C_DIM, C_DIM, C_DIM, smem_raw, acc);

    const int tid  = threadIdx.x;
    const int wid  = tid >> 5;
    const int lane = tid & 31;
    const int warp_m = (wid & 1) * 64;
    const int warp_n = (wid >> 1) * 64;
    const int gq = lane >> 2;
    const int tq = lane & 3;

#pragma unroll
    for (int i = 0; i < 4; i++) {
#pragma unroll
        for (int j = 0; j < 8; j++) {
            const int col = n0 + warp_n + j * 8 + tq * 2;
#pragma unroll
            for (int h = 0; h < 2; h++) {
                const int row = m0 + warp_m + i * 16 + gq + h * 8;
                float2 bb = *reinterpret_cast<const float2*>(bias + col);
                float v0 = acc[i][j][2 * h]     + bb.x;
                float v1 = acc[i][j][2 * h + 1] + bb.y;
                if (z == 0) {
                    *reinterpret_cast<uint32_t*>(Q16 + (size_t)row * C_DIM + col) =
                        packh(__float2half(v0), __float2half(v1));
                } else if (z == 1) {
                    *reinterpret_cast<uint32_t*>(K16 + (size_t)row * C_DIM + col) =
                        packh(__float2half(v0), __float2half(v1));
                } else {
                    Vt16[(size_t)col * M_ALL + row]       = __float2half(v0);
                    Vt16[(size_t)(col + 1) * M_ALL + row] = __float2half(v1);
                }
            }
        }
    }
}

// ---------------------------------------------------------------------------
// Pipelined stage kernel: blockIdx.x ranges dispatch to
//   [0, nScore)              : scores CTA (batch zScore)   16x16 tiles
//   [nScore, +nAttn)         : attnV CTA  (batch zAttn)    8x16 tiles
//   [.., +nOut)              : outproj CTA(batch zOut)     8x16 tiles
//   [.., +nSoft)             : softmax row (batch zSoft)   128 thr x 16 elems
// ---------------------------------------------------------------------------
__global__ __launch_bounds__(128, 2)
void stage_k(int nScore, int zScore, int nAttn, int zAttn,
             int nOut, int zOut, int nSoft, int zSoft,
             const half* __restrict__ Q16, const half* __restrict__ K16,
             float* __restrict__ S, const half* __restrict__ P16,
             const half* __restrict__ Vt16, const float* __restrict__ x,
             half* __restrict__ T16, const half* __restrict__ Wo16,
             const float* __restrict__ bo, float* __restrict__ out)
{
    extern __shared__ __align__(16) char smem_raw[];
    const int bx  = blockIdx.x;
    const int tid = threadIdx.x;
    const long long sQ = (long long)S_DIM * C_DIM;
    const long long sS = (long long)S_DIM * S_DIM;

    if (bx < nScore + nAttn + nOut) {
        // ---- GEMM paths ----
        float acc[4][8][4];
#pragma unroll
        for (int i = 0; i < 4; i++)
#pragma unroll
            for (int j = 0; j < 8; j++)
#pragma unroll
                for (int c = 0; c < 4; c++) acc[i][j][c] = 0.f;

        int mode, m0, n0, z;
        if (bx < nScore) {
            mode = 0; z = zScore;
            m0 = (bx >> 4) * 128; n0 = (bx & 15) * 128;
            gemm_core1(Q16 + z * sQ + (size_t)m0 * C_DIM,
                       K16 + z * sQ + (size_t)n0 * C_DIM,
                       C_DIM, C_DIM, C_DIM, smem_raw, acc);
        } else if (bx < nScore + nAttn) {
            mode = 1; z = zAttn;
            const int i2 = bx - nScore;
            m0 = (i2 >> 3) * 128; n0 = (i2 & 7) * 128;
            gemm_core1(P16 + z * sS + (size_t)m0 * S_DIM,
                       Vt16 + z * S_DIM + (size_t)n0 * M_ALL,
                       S_DIM, M_ALL, S_DIM, smem_raw, acc);
        } else {
            mode = 2; z = zOut;
            const int i2 = bx - nScore - nAttn;
            m0 = (i2 >> 3) * 128; n0 = (i2 & 7) * 128;
            gemm_core1(T16 + z * sQ + (size_t)m0 * C_DIM,
                       Wo16 + (size_t)n0 * C_DIM,
                       C_DIM, C_DIM, C_DIM, smem_raw, acc);
        }

        const int wid  = tid >> 5;
        const int lane = tid & 31;
        const int warp_m = (wid & 1) * 64;
        const int warp_n = (wid >> 1) * 64;
        const int gq = lane >> 2;
        const int tq = lane & 3;

#pragma unroll
        for (int i = 0; i < 4; i++) {
#pragma unroll
            for (int j = 0; j < 8; j++) {
                const int col = n0 + warp_n + j * 8 + tq * 2;
#pragma unroll
                for (int h = 0; h < 2; h++) {
                    const int row = m0 + warp_m + i * 16 + gq + h * 8;
                    float v0 = acc[i][j][2 * h];
                    float v1 = acc[i][j][2 * h + 1];
                    if (mode == 0) {
                        // scores: *1/32, fp32 out
                        *reinterpret_cast<float2*>(
                            S + z * sS + (size_t)row * S_DIM + col) =
                            make_float2(v0 * 0.03125f, v1 * 0.03125f);
                    } else if (mode == 1) {
                        // attnV: + x residual, fp16 out T
                        float2 r = *reinterpret_cast<const float2*>(
                            x + z * sQ + (size_t)row * C_DIM + col);
                        *reinterpret_cast<uint32_t*>(
                            T16 + z * sQ + (size_t)row * C_DIM + col) =
                            packh(__float2half(v0 + r.x), __float2half(v1 + r.y));
                    } else {
                        // outproj: + bo, fp32 final out
                        float2 bb = *reinterpret_cast<const float2*>(bo + col);
                        *reinterpret_cast<float2*>(
                            out + (size_t)(z * S_DIM + row) * C_DIM + col) =
                            make_float2(v0 + bb.x, v1 + bb.y);
                    }
                }
            }
        }
    } else {
        // ---- softmax path: one row of 2048, 128 threads x 16 elems ----
        const int r = bx - (nScore + nAttn + nOut);
        const long long row = (long long)zSoft * S_DIM + r;
        const float* p = S + row * S_DIM;
        float* sred = reinterpret_cast<float*>(smem_raw);
        const int w = tid >> 5, l = tid & 31;

        float v[16];
#pragma unroll
        for (int c = 0; c < 4; c++) {
            float4 t = *reinterpret_cast<const float4*>(p + tid * 16 + c * 4);
            v[c * 4 + 0] = t.x; v[c * 4 + 1] = t.y;
            v[c * 4 + 2] = t.z; v[c * 4 + 3] = t.w;
        }

        float m = v[0];
#pragma unroll
        for (int j = 1; j < 16; j++) m = fmaxf(m, v[j]);
#pragma unroll
        for (int off = 16; off >= 1; off >>= 1)
            m = fmaxf(m, __shfl_xor_sync(0xffffffffu, m, off));
        if (l == 0) sred[w] = m;
        __syncthreads();
        float bm = fmaxf(fmaxf(sred[0], sred[1]), fmaxf(sred[2], sred[3]));
        __syncthreads();

        float s = 0.f;
#pragma unroll
        for (int j = 0; j < 16; j++) { v[j] = expf(v[j] - bm); s += v[j]; }
#pragma unroll
        for (int off = 16; off >= 1; off >>= 1)
            s += __shfl_xor_sync(0xffffffffu, s, off);
        if (l == 0) sred[4 + w] = s;
        __syncthreads();
        float tot = (sred[4] + sred[5]) + (sred[6] + sred[7]);

        const float inv = 1.f / tot;
        half hh[16];
#pragma unroll
        for (int j = 0; j < 16; j++) hh[j] = __float2half(v[j] * inv);

        half* po = const_cast<half*>(P16) + row * S_DIM + tid * 16;
#pragma unroll
        for (int c = 0; c < 4; c++) {
            *reinterpret_cast<uint2*>(po + c * 4) =
                make_uint2(packh(hh[c * 4], hh[c * 4 + 1]),
                           packh(hh[c * 4 + 2], hh[c * 4 + 3]));
        }
    }
}

// ---------------------------------------------------------------------------
extern "C" void kernel_launch(void* const* d_in, const int* in_sizes, int n_in,
                              void* d_out, int out_size)
{
    (void)in_sizes; (void)n_in; (void)out_size;
    const float* x  = (const float*)d_in[0];
    const float* ce = (const float*)d_in[1];
    const float* Wq = (const float*)d_in[2];
    const float* bq = (const float*)d_in[3];
    const float* Wk = (const float*)d_in[4];
    const float* bk = (const float*)d_in[5];
    const float* Wv = (const float*)d_in[6];
    const float* bv = (const float*)d_in[7];
    const float* Wo = (const float*)d_in[8];
    const float* bo = (const float*)d_in[9];
    float* out = (float*)d_out;

    float* S;
    half *x16, *ce16, *Wq16, *Wk16, *Wv16, *Wo16;
    half *Q16, *K16, *Vt16, *P16, *T16;
    cudaGetSymbolAddress((void**)&S,    g_S);
    cudaGetSymbolAddress((void**)&x16,  g_x16);  cudaGetSymbolAddress((void**)&ce16, g_ce16);
    cudaGetSymbolAddress((void**)&Wq16, g_Wq16); cudaGetSymbolAddress((void**)&Wk16, g_Wk16);
    cudaGetSymbolAddress((void**)&Wv16, g_Wv16); cudaGetSymbolAddress((void**)&Wo16, g_Wo16);
    cudaGetSymbolAddress((void**)&Q16,  g_Q16);  cudaGetSymbolAddress((void**)&K16,  g_K16);
    cudaGetSymbolAddress((void**)&Vt16, g_Vt16); cudaGetSymbolAddress((void**)&P16,  g_P16);
    cudaGetSymbolAddress((void**)&T16,  g_T16);

    cudaFuncSetAttribute(gemm_qkv, cudaFuncAttributeMaxDynamicSharedMemorySize, SMEM1);
    cudaFuncSetAttribute(stage_k,  cudaFuncAttributeMaxDynamicSharedMemorySize, SMEM1);

    round_all<<<20480, 256>>>(
        (const float4*)x, (const float4*)ce, (const float4*)Wq,
        (const float4*)Wk, (const float4*)Wv, (const float4*)Wo,
        (uint2*)x16, (uint2*)ce16, (uint2*)Wq16, (uint2*)Wk16,
        (uint2*)Wv16, (uint2*)Wo16);

    gemm_qkv<<<dim3(8, 64, 3), 128, SMEM1>>>(
        x16, ce16, Wq16, Wk16, Wv16, bq, bk, bv, Q16, K16, Vt16);

    // pipelined stages (dependencies satisfied by launch order):
    // Ln: scores z | attn z' | out z'' | softmax z'''
#define STAGE(ns, zs, na, za, no, zo, nf, zf) \
    stage_k<<<(ns) + (na) + (no) + (nf), 128, SMEM1>>>( \
        ns, zs, na, za, no, zo, nf, zf, \
        Q16, K16, S, P16, Vt16, x, T16, Wo16, bo, out)

    STAGE(256, 0,   0, 0,   0, 0,    0, 0);   // scores b0
    STAGE(256, 1,   0, 0,   0, 0, 2048, 0);   // scores b1 | soft b0
    STAGE(256, 2, 128, 0,   0, 0, 2048, 1);   // scores b2 | attn b0 | soft b1
    STAGE(256, 3, 128, 1, 128, 0, 2048, 2);   // scores b3 | attn b1 | out b0 | soft b2
    STAGE(  0, 0, 128, 2, 128, 1, 2048, 3);   // attn b2 | out b1 | soft b3
    STAGE(  0, 0, 128, 3, 128, 2,    0, 0);   // attn b3 | out b2
    STAGE(  0, 0,   0, 0, 128, 3,    0, 0);   // out b3
#undef STAGE
}

// round 14
// speedup vs baseline: 1.4255x; 1.4255x over previous
#include <cuda_runtime.h>
#include <cuda_fp16.h>
#include <cstdint>
#include <math.h>

// ---------------------------------------------------------------------------
// SpatialTransformer via mma.sync fp16 (HMMA).
// Round 14: round-12 structure (separate launches, proven 566us) with
// 1-pass out-projection (T rounded fp16, Wo rounded fp16) -> less MMA work.
// ---------------------------------------------------------------------------

#define B_DIM 4
#define S_DIM 2048
#define C_DIM 1024
#define M_ALL (B_DIM * S_DIM)   // 8192

__device__ float g_S[(long long)B_DIM * S_DIM * S_DIM];  // scores, 64 MB
__device__ half g_x16[M_ALL * C_DIM], g_ce16[M_ALL * C_DIM];
__device__ half g_Wq16[C_DIM * C_DIM], g_Wk16[C_DIM * C_DIM];
__device__ half g_Wv16[C_DIM * C_DIM], g_Wo16[C_DIM * C_DIM];
__device__ half g_Q16[M_ALL * C_DIM], g_K16[M_ALL * C_DIM];
__device__ half g_Vt16[C_DIM * M_ALL];                      // V^T [C][B*S]
__device__ half g_P16[(long long)B_DIM * S_DIM * S_DIM];
__device__ half g_T16[M_ALL * C_DIM];                       // x + attended (fp16)

__device__ __forceinline__ uint32_t smem_u32(const void* p) {
    uint32_t a;
    asm("{ .reg .u64 t; cvta.to.shared.u64 t, %1; cvt.u32.u64 %0, t; }"
        : "=r"(a) : "l"(p));
    return a;
}

#define LDMX4(r0, r1, r2, r3, addr) \
    asm volatile("ldmatrix.sync.aligned.m8n8.x4.shared.b16 {%0,%1,%2,%3}, [%4];" \
                 : "=r"(r0), "=r"(r1), "=r"(r2), "=r"(r3) : "r"(addr))
#define MMA16816(d, a, b) \
    asm volatile("mma.sync.aligned.m16n8k16.row.col.f32.f16.f16.f32 " \
                 "{%0,%1,%2,%3}, {%4,%5,%6,%7}, {%8,%9}, {%0,%1,%2,%3};" \
                 : "+f"((d)[0]), "+f"((d)[1]), "+f"((d)[2]), "+f"((d)[3]) \
                 : "r"((a)[0]), "r"((a)[1]), "r"((a)[2]), "r"((a)[3]), \
                   "r"((b)[0]), "r"((b)[1]))
#define CP_ASYNC16(dst, src) \
    asm volatile("cp.async.cg.shared.global [%0], [%1], 16;" \
                 :: "r"(dst), "l"(src) : "memory")
#define CP_COMMIT() asm volatile("cp.async.commit_group;" ::: "memory")

#define KT        32
#define ROW_H     40
#define TILE_H    (128 * ROW_H)          // halves (5120)
#define STAGE1_H  (2 * TILE_H)
#define SMEM1     (3 * STAGE1_H * 2)     // 61440 B

__device__ __forceinline__ uint32_t packh(half a, half b) {
    __half2 t; t.x = a; t.y = b;
    return *reinterpret_cast<uint32_t*>(&t);
}

// ---------------------------------------------------------------------------
// Fused rounding pass: all six fp32 tensors -> fp16.
// ---------------------------------------------------------------------------
__global__ __launch_bounds__(256)
void round_all(const float4* __restrict__ x,  const float4* __restrict__ ce,
               const float4* __restrict__ Wq, const float4* __restrict__ Wk,
               const float4* __restrict__ Wv, const float4* __restrict__ Wo,
               uint2* __restrict__ x16,  uint2* __restrict__ ce16,
               uint2* __restrict__ Wq16, uint2* __restrict__ Wk16,
               uint2* __restrict__ Wv16, uint2* __restrict__ Wo16)
{
    const int b = blockIdx.x;
    const float4* in; uint2* o; int lb;
    if (b < 8192)       { in = x;  o = x16;  lb = b; }
    else if (b < 16384) { in = ce; o = ce16; lb = b - 8192; }
    else if (b < 17408) { in = Wq; o = Wq16; lb = b - 16384; }
    else if (b < 18432) { in = Wk; o = Wk16; lb = b - 17408; }
    else if (b < 19456) { in = Wv; o = Wv16; lb = b - 18432; }
    else                { in = Wo; o = Wo16; lb = b - 19456; }

    const int i = lb * 256 + threadIdx.x;
    float4 v = in[i];
    o[i] = make_uint2(packh(__float2half(v.x), __float2half(v.y)),
                      packh(__float2half(v.z), __float2half(v.w)));
}

// ---------------------------------------------------------------------------
// 1-pass mainloop: acc += A@B^T. 2 smem tiles/stage, 3-stage ring.
// ---------------------------------------------------------------------------
__device__ __forceinline__ void gemm_core1(
    const half* __restrict__ Ag, const half* __restrict__ Bg,
    int ldA, int ldB, int K, char* smem_raw, float acc[4][8][4])
{
    const uint32_t sm_base = smem_u32(smem_raw);
    const int tid  = threadIdx.x;
    const int lane = tid & 31;
    const int wid  = tid >> 5;

    const int warp_m = (wid & 1) * 64;
    const int warp_n = (wid >> 1) * 64;

    const int r0 = tid >> 2;
    const int kc = (tid & 3) * 8;

    const int arow  = warp_m + (lane & 15);
    const int acolr = (lane >> 4) << 3;
    const int brow_off = ((lane >> 4) << 3) + (lane & 7);
    const int bcolr = lane & 8;

    const int NK = K >> 5;

    auto load_stage = [&](int buf, int kt) {
        const uint32_t sbase = sm_base + (uint32_t)(buf * STAGE1_H) * 2;
        const int kk = kt * KT + kc;
#pragma unroll
        for (int rr = 0; rr < 4; rr++) {
            const int row = r0 + rr * 32;
            const uint32_t so = (uint32_t)(row * ROW_H + kc) * 2;
            CP_ASYNC16(sbase + so,                          Ag + (size_t)row * ldA + kk);
            CP_ASYNC16(sbase + (uint32_t)(TILE_H * 2) + so, Bg + (size_t)row * ldB + kk);
        }
    };

    load_stage(0, 0);
    CP_COMMIT();
    load_stage(1, 1);
    CP_COMMIT();

    for (int kt = 0; kt < NK; ++kt) {
        if (kt + 2 < NK) {
            load_stage((kt + 2) % 3, kt + 2);
            CP_COMMIT();
        }
        const int rem = NK - 1 - kt;
        if (rem >= 2)      asm volatile("cp.async.wait_group 2;" ::: "memory");
        else if (rem == 1) asm volatile("cp.async.wait_group 1;" ::: "memory");
        else               asm volatile("cp.async.wait_group 0;" ::: "memory");
        __syncthreads();

        const uint32_t stg = sm_base + (uint32_t)((kt % 3) * STAGE1_H) * 2;

        uint32_t af[2][4][4];
        uint32_t bb[2][8][2];

#pragma unroll
        for (int half_ = 0; half_ < 2; ++half_) {
            const int kk = half_ * 16;
#pragma unroll
            for (int i = 0; i < 4; i++) {
                const uint32_t byt = (uint32_t)(((arow + i * 16) * ROW_H + kk + acolr) * 2);
                LDMX4(af[half_][i][0], af[half_][i][1], af[half_][i][2], af[half_][i][3],
                      stg + byt);
            }
#pragma unroll
            for (int jj = 0; jj < 8; jj += 2) {
                const uint32_t byt =
                    (uint32_t)(((warp_n + jj * 8 + brow_off) * ROW_H + kk + bcolr) * 2);
                LDMX4(bb[half_][jj][0], bb[half_][jj][1],
                      bb[half_][jj + 1][0], bb[half_][jj + 1][1],
                      stg + (uint32_t)(TILE_H * 2) + byt);
            }
        }

#pragma unroll
        for (int half_ = 0; half_ < 2; ++half_)
#pragma unroll
            for (int i = 0; i < 4; i++)
#pragma unroll
                for (int j = 0; j < 8; j++)
                    MMA16816(acc[i][j], af[half_][i], bb[half_][j]);

        __syncthreads();
    }
}

// ---------------------------------------------------------------------------
// Fused Q/K/V projection (1-pass): grid (8, 64, 3).
// ---------------------------------------------------------------------------
__global__ __launch_bounds__(128, 2)
void gemm_qkv(const half* __restrict__ x16, const half* __restrict__ ce16,
              const half* __restrict__ Wq16, const half* __restrict__ Wk16,
              const half* __restrict__ Wv16,
              const float* __restrict__ bq, const float* __restrict__ bk,
              const float* __restrict__ bv,
              half* __restrict__ Q16, half* __restrict__ K16,
              half* __restrict__ Vt16)
{
    extern __shared__ __align__(16) char smem_raw[];
    const int z  = blockIdx.z;
    const int m0 = blockIdx.y * 128;
    const int n0 = blockIdx.x * 128;

    const half *A_, *B_;
    const float* bias;
    if (z == 0)      { A_ = x16;  B_ = Wq16; bias = bq; }
    else if (z == 1) { A_ = ce16; B_ = Wk16; bias = bk; }
    else             { A_ = ce16; B_ = Wv16; bias = bv; }

    float acc[4][8][4];
#pragma unroll
    for (int i = 0; i < 4; i++)
#pragma unroll
        for (int j = 0; j < 8; j++)
#pragma unroll
            for (int c = 0; c < 4; c++) acc[i][j][c] = 0.f;

    gemm_core1(A_ + (size_t)m0 * C_DIM, B_ + (size_t)n0 * C_DIM,
               C_DIM, C_DIM, C_DIM, smem_raw, acc);

    const int tid  = threadIdx.x;
    const int wid  = tid >> 5;
    const int lane = tid & 31;
    const int warp_m = (wid & 1) * 64;
    const int warp_n = (wid >> 1) * 64;
    const int gq = lane >> 2;
    const int tq = lane & 3;

#pragma unroll
    for (int i = 0; i < 4; i++) {
#pragma unroll
        for (int j = 0; j < 8; j++) {
            const int col = n0 + warp_n + j * 8 + tq * 2;
#pragma unroll
            for (int h = 0; h < 2; h++) {
                const int row = m0 + warp_m + i * 16 + gq + h * 8;
                float2 bb = *reinterpret_cast<const float2*>(bias + col);
                float v0 = acc[i][j][2 * h]     + bb.x;
                float v1 = acc[i][j][2 * h + 1] + bb.y;
                if (z == 0) {
                    *reinterpret_cast<uint32_t*>(Q16 + (size_t)row * C_DIM + col) =
                        packh(__float2half(v0), __float2half(v1));
                } else if (z == 1) {
                    *reinterpret_cast<uint32_t*>(K16 + (size_t)row * C_DIM + col) =
                        packh(__float2half(v0), __float2half(v1));
                } else {
                    Vt16[(size_t)col * M_ALL + row]       = __float2half(v0);
                    Vt16[(size_t)(col + 1) * M_ALL + row] = __float2half(v1);
                }
            }
        }
    }
}

// ---------------------------------------------------------------------------
// 1-pass generic GEMM.
// OUT_MODE: 0 fp32 out (*alpha), 1 fp16 out (+residual), 2 fp32 out (+bias)
// ---------------------------------------------------------------------------
template<int OUT_MODE>
__global__ __launch_bounds__(128, 2)
void gemm1(const half* __restrict__ Ag, const half* __restrict__ Bg,
           const float* __restrict__ Rb,
           float* __restrict__ Cf, half* __restrict__ Ch,
           int K, float alpha, int ldA, int ldB, int ldC,
           long long sA, long long sB, long long sC, long long sR)
{
    extern __shared__ __align__(16) char smem_raw[];
    const int z  = blockIdx.z;
    const int m0 = blockIdx.y * 128;
    const int n0 = blockIdx.x * 128;

    float acc[4][8][4];
#pragma unroll
    for (int i = 0; i < 4; i++)
#pragma unroll
        for (int j = 0; j < 8; j++)
#pragma unroll
            for (int c = 0; c < 4; c++) acc[i][j][c] = 0.f;

    gemm_core1(Ag + z * sA + (size_t)m0 * ldA, Bg + z * sB + (size_t)n0 * ldB,
               ldA, ldB, K, smem_raw, acc);

    const int tid  = threadIdx.x;
    const int wid  = tid >> 5;
    const int lane = tid & 31;
    const int warp_m = (wid & 1) * 64;
    const int warp_n = (wid >> 1) * 64;
    const int gq = lane >> 2;
    const int tq = lane & 3;

#pragma unroll
    for (int i = 0; i < 4; i++) {
#pragma unroll
        for (int j = 0; j < 8; j++) {
            const int col = n0 + warp_n + j * 8 + tq * 2;
#pragma unroll
            for (int h = 0; h < 2; h++) {
                const int row = m0 + warp_m + i * 16 + gq + h * 8;
                float v0 = acc[i][j][2 * h];
                float v1 = acc[i][j][2 * h + 1];
                if (OUT_MODE == 0) {
                    // scores: * alpha, fp32
                    *reinterpret_cast<float2*>(Cf + z * sC + (size_t)row * ldC + col)
                        = make_float2(v0 * alpha, v1 * alpha);
                } else if (OUT_MODE == 1) {
                    // attnV: + residual (fp32 Rb), fp16 out
                    float2 r = *reinterpret_cast<const float2*>(
                        Rb + z * sR + (size_t)row * ldC + col);
                    *reinterpret_cast<uint32_t*>(Ch + z * sC + (size_t)row * ldC + col) =
                        packh(__float2half(v0 + r.x), __float2half(v1 + r.y));
                } else {
                    // outproj: + bias, fp32 out
                    float2 bb = *reinterpret_cast<const float2*>(Rb + col);
                    *reinterpret_cast<float2*>(Cf + z * sC + (size_t)row * ldC + col)
                        = make_float2(v0 + bb.x, v1 + bb.y);
                }
            }
        }
    }
}

// ---------------------------------------------------------------------------
// Row softmax (2048/row) -> fp16 probabilities.
// ---------------------------------------------------------------------------
__global__ __launch_bounds__(256)
void softmax2048(const float* __restrict__ S, half* __restrict__ P)
{
    const long long row = blockIdx.x;
    const float* p = S + row * 2048;
    const int tid = threadIdx.x;
    const int w = tid >> 5, l = tid & 31;

    float v[8];
    {
        float4 x0 = *reinterpret_cast<const float4*>(p + tid * 8);
        float4 x1 = *reinterpret_cast<const float4*>(p + tid * 8 + 4);
        v[0] = x0.x; v[1] = x0.y; v[2] = x0.z; v[3] = x0.w;
        v[4] = x1.x; v[5] = x1.y; v[6] = x1.z; v[7] = x1.w;
    }
    __shared__ float smax[8], ssum[8];

    float m = v[0];
#pragma unroll
    for (int j = 1; j < 8; j++) m = fmaxf(m, v[j]);
#pragma unroll
    for (int off = 16; off >= 1; off >>= 1)
        m = fmaxf(m, __shfl_xor_sync(0xffffffffu, m, off));
    if (l == 0) smax[w] = m;
    __syncthreads();
    float bm = smax[0];
#pragma unroll
    for (int j = 1; j < 8; j++) bm = fmaxf(bm, smax[j]);

    float s = 0.f;
#pragma unroll
    for (int j = 0; j < 8; j++) { v[j] = expf(v[j] - bm); s += v[j]; }
#pragma unroll
    for (int off = 16; off >= 1; off >>= 1)
        s += __shfl_xor_sync(0xffffffffu, s, off);
    if (l == 0) ssum[w] = s;
    __syncthreads();
    float tot = ssum[0];
#pragma unroll
    for (int j = 1; j < 8; j++) tot += ssum[j];

    const float inv = 1.f / tot;
    half hh[8];
#pragma unroll
    for (int j = 0; j < 8; j++) hh[j] = __float2half(v[j] * inv);

    const long long ob = row * 2048 + tid * 8;
    *reinterpret_cast<uint2*>(P + ob) =
        make_uint2(packh(hh[0], hh[1]), packh(hh[2], hh[3]));
    *reinterpret_cast<uint2*>(P + ob + 4) =
        make_uint2(packh(hh[4], hh[5]), packh(hh[6], hh[7]));
}

// ---------------------------------------------------------------------------
extern "C" void kernel_launch(void* const* d_in, const int* in_sizes, int n_in,
                              void* d_out, int out_size)
{
    (void)in_sizes; (void)n_in; (void)out_size;
    const float* x  = (const float*)d_in[0];
    const float* ce = (const float*)d_in[1];
    const float* Wq = (const float*)d_in[2];
    const float* bq = (const float*)d_in[3];
    const float* Wk = (const float*)d_in[4];
    const float* bk = (const float*)d_in[5];
    const float* Wv = (const float*)d_in[6];
    const float* bv = (const float*)d_in[7];
    const float* Wo = (const float*)d_in[8];
    const float* bo = (const float*)d_in[9];
    float* out = (float*)d_out;

    float* S;
    half *x16, *ce16, *Wq16, *Wk16, *Wv16, *Wo16;
    half *Q16, *K16, *Vt16, *P16, *T16;
    cudaGetSymbolAddress((void**)&S,    g_S);
    cudaGetSymbolAddress((void**)&x16,  g_x16);  cudaGetSymbolAddress((void**)&ce16, g_ce16);
    cudaGetSymbolAddress((void**)&Wq16, g_Wq16); cudaGetSymbolAddress((void**)&Wk16, g_Wk16);
    cudaGetSymbolAddress((void**)&Wv16, g_Wv16); cudaGetSymbolAddress((void**)&Wo16, g_Wo16);
    cudaGetSymbolAddress((void**)&Q16,  g_Q16);  cudaGetSymbolAddress((void**)&K16,  g_K16);
    cudaGetSymbolAddress((void**)&Vt16, g_Vt16); cudaGetSymbolAddress((void**)&P16,  g_P16);
    cudaGetSymbolAddress((void**)&T16,  g_T16);

    cudaFuncSetAttribute(gemm_qkv, cudaFuncAttributeMaxDynamicSharedMemorySize, SMEM1);
    cudaFuncSetAttribute(gemm1<0>, cudaFuncAttributeMaxDynamicSharedMemorySize, SMEM1);
    cudaFuncSetAttribute(gemm1<1>, cudaFuncAttributeMaxDynamicSharedMemorySize, SMEM1);
    cudaFuncSetAttribute(gemm1<2>, cudaFuncAttributeMaxDynamicSharedMemorySize, SMEM1);

    round_all<<<20480, 256>>>(
        (const float4*)x, (const float4*)ce, (const float4*)Wq,
        (const float4*)Wk, (const float4*)Wv, (const float4*)Wo,
        (uint2*)x16, (uint2*)ce16, (uint2*)Wq16, (uint2*)Wk16,
        (uint2*)Wv16, (uint2*)Wo16);

    const long long sQ = (long long)S_DIM * C_DIM;
    const long long sS = (long long)S_DIM * S_DIM;

    // fused Q/K/V projections (1536 CTAs, 1-pass)
    gemm_qkv<<<dim3(8, 64, 3), 128, SMEM1>>>(
        x16, ce16, Wq16, Wk16, Wv16, bq, bk, bv, Q16, K16, Vt16);

    // scores: per-batch Q @ K^T / 32 -> fp32 S
    gemm1<0><<<dim3(16, 16, B_DIM), 128, SMEM1>>>(
        Q16, K16, nullptr, S, nullptr,
        C_DIM, 0.03125f, C_DIM, C_DIM, S_DIM, sQ, sQ, sS, 0);

    softmax2048<<<M_ALL, 256>>>(S, P16);

    // attended + residual -> fp16 T (single plane)
    gemm1<1><<<dim3(8, 16, B_DIM), 128, SMEM1>>>(
        P16, Vt16, x, nullptr, T16,
        S_DIM, 1.f, S_DIM, M_ALL, C_DIM, sS, S_DIM, sQ, sQ);

    // output projection (1-pass, fp32 out)
    gemm1<2><<<dim3(8, 64, 1), 128, SMEM1>>>(
        T16, Wo16, bo, out, nullptr,
        C_DIM, 1.f, C_DIM, C_DIM, C_DIM, 0, 0, (long long)S_DIM * C_DIM, 0);
}

// round 15
// speedup vs baseline: 1.5812x; 1.1092x over previous
#include <cuda_runtime.h>
#include <cuda_fp16.h>
#include <cstdint>
#include <math.h>

// ---------------------------------------------------------------------------
// SpatialTransformer via mma.sync fp16 (HMMA).
// Round 15: round-14 math/schedule; gemm_core1 uses 4-stage cp.async ring at
// prefetch distance 2 with a SINGLE __syncthreads per ktile (trailing
// anti-overwrite barrier eliminated by the extra slack stage).
// ---------------------------------------------------------------------------

#define B_DIM 4
#define S_DIM 2048
#define C_DIM 1024
#define M_ALL (B_DIM * S_DIM)   // 8192

__device__ float g_S[(long long)B_DIM * S_DIM * S_DIM];  // scores, 64 MB
__device__ half g_x16[M_ALL * C_DIM], g_ce16[M_ALL * C_DIM];
__device__ half g_Wq16[C_DIM * C_DIM], g_Wk16[C_DIM * C_DIM];
__device__ half g_Wv16[C_DIM * C_DIM], g_Wo16[C_DIM * C_DIM];
__device__ half g_Q16[M_ALL * C_DIM], g_K16[M_ALL * C_DIM];
__device__ half g_Vt16[C_DIM * M_ALL];                      // V^T [C][B*S]
__device__ half g_P16[(long long)B_DIM * S_DIM * S_DIM];
__device__ half g_T16[M_ALL * C_DIM];                       // x + attended (fp16)

__device__ __forceinline__ uint32_t smem_u32(const void* p) {
    uint32_t a;
    asm("{ .reg .u64 t; cvta.to.shared.u64 t, %1; cvt.u32.u64 %0, t; }"
        : "=r"(a) : "l"(p));
    return a;
}

#define LDMX4(r0, r1, r2, r3, addr) \
    asm volatile("ldmatrix.sync.aligned.m8n8.x4.shared.b16 {%0,%1,%2,%3}, [%4];" \
                 : "=r"(r0), "=r"(r1), "=r"(r2), "=r"(r3) : "r"(addr))
#define MMA16816(d, a, b) \
    asm volatile("mma.sync.aligned.m16n8k16.row.col.f32.f16.f16.f32 " \
                 "{%0,%1,%2,%3}, {%4,%5,%6,%7}, {%8,%9}, {%0,%1,%2,%3};" \
                 : "+f"((d)[0]), "+f"((d)[1]), "+f"((d)[2]), "+f"((d)[3]) \
                 : "r"((a)[0]), "r"((a)[1]), "r"((a)[2]), "r"((a)[3]), \
                   "r"((b)[0]), "r"((b)[1]))
#define CP_ASYNC16(dst, src) \
    asm volatile("cp.async.cg.shared.global [%0], [%1], 16;" \
                 :: "r"(dst), "l"(src) : "memory")
#define CP_COMMIT() asm volatile("cp.async.commit_group;" ::: "memory")

#define KT        32
#define ROW_H     40
#define TILE_H    (128 * ROW_H)          // halves (5120)
#define STAGE1_H  (2 * TILE_H)           // A + B tile per stage (20480 B)
#define NSTAGE    4
#define SMEM1     (NSTAGE * STAGE1_H * 2)   // 81920 B  (x2 CTAs = 160KB)

__device__ __forceinline__ uint32_t packh(half a, half b) {
    __half2 t; t.x = a; t.y = b;
    return *reinterpret_cast<uint32_t*>(&t);
}

// ---------------------------------------------------------------------------
// Fused rounding pass: all six fp32 tensors -> fp16.
// ---------------------------------------------------------------------------
__global__ __launch_bounds__(256)
void round_all(const float4* __restrict__ x,  const float4* __restrict__ ce,
               const float4* __restrict__ Wq, const float4* __restrict__ Wk,
               const float4* __restrict__ Wv, const float4* __restrict__ Wo,
               uint2* __restrict__ x16,  uint2* __restrict__ ce16,
               uint2* __restrict__ Wq16, uint2* __restrict__ Wk16,
               uint2* __restrict__ Wv16, uint2* __restrict__ Wo16)
{
    const int b = blockIdx.x;
    const float4* in; uint2* o; int lb;
    if (b < 8192)       { in = x;  o = x16;  lb = b; }
    else if (b < 16384) { in = ce; o = ce16; lb = b - 8192; }
    else if (b < 17408) { in = Wq; o = Wq16; lb = b - 16384; }
    else if (b < 18432) { in = Wk; o = Wk16; lb = b - 17408; }
    else if (b < 19456) { in = Wv; o = Wv16; lb = b - 18432; }
    else                { in = Wo; o = Wo16; lb = b - 19456; }

    const int i = lb * 256 + threadIdx.x;
    float4 v = in[i];
    o[i] = make_uint2(packh(__float2half(v.x), __float2half(v.y)),
                      packh(__float2half(v.z), __float2half(v.w)));
}

// ---------------------------------------------------------------------------
// 1-pass mainloop: acc += A@B^T. 4-stage ring, prefetch distance 2,
// ONE __syncthreads per ktile.
// ---------------------------------------------------------------------------
__device__ __forceinline__ void gemm_core1(
    const half* __restrict__ Ag, const half* __restrict__ Bg,
    int ldA, int ldB, int K, char* smem_raw, float acc[4][8][4])
{
    const uint32_t sm_base = smem_u32(smem_raw);
    const int tid  = threadIdx.x;
    const int lane = tid & 31;
    const int wid  = tid >> 5;

    const int warp_m = (wid & 1) * 64;
    const int warp_n = (wid >> 1) * 64;

    const int r0 = tid >> 2;
    const int kc = (tid & 3) * 8;

    const int arow  = warp_m + (lane & 15);
    const int acolr = (lane >> 4) << 3;
    const int brow_off = ((lane >> 4) << 3) + (lane & 7);
    const int bcolr = lane & 8;

    const int NK = K >> 5;

    auto load_stage = [&](int buf, int kt) {
        const uint32_t sbase = sm_base + (uint32_t)(buf * STAGE1_H) * 2;
        const int kk = kt * KT + kc;
#pragma unroll
        for (int rr = 0; rr < 4; rr++) {
            const int row = r0 + rr * 32;
            const uint32_t so = (uint32_t)(row * ROW_H + kc) * 2;
            CP_ASYNC16(sbase + so,                          Ag + (size_t)row * ldA + kk);
            CP_ASYNC16(sbase + (uint32_t)(TILE_H * 2) + so, Bg + (size_t)row * ldB + kk);
        }
    };

    load_stage(0, 0);
    CP_COMMIT();
    load_stage(1, 1);
    CP_COMMIT();

    for (int kt = 0; kt < NK; ++kt) {
        if (kt + 2 < NK) {
            load_stage((kt + 2) & 3, kt + 2);
            CP_COMMIT();
        }
        const int rem = NK - 1 - kt;
        if (rem >= 2)      asm volatile("cp.async.wait_group 2;" ::: "memory");
        else if (rem == 1) asm volatile("cp.async.wait_group 1;" ::: "memory");
        else               asm volatile("cp.async.wait_group 0;" ::: "memory");
        __syncthreads();   // single barrier per ktile (slack stage prevents overwrite)

        const uint32_t stg = sm_base + (uint32_t)((kt & 3) * STAGE1_H) * 2;

        uint32_t af[2][4][4];
        uint32_t bb[2][8][2];

#pragma unroll
        for (int half_ = 0; half_ < 2; ++half_) {
            const int kk = half_ * 16;
#pragma unroll
            for (int i = 0; i < 4; i++) {
                const uint32_t byt = (uint32_t)(((arow + i * 16) * ROW_H + kk + acolr) * 2);
                LDMX4(af[half_][i][0], af[half_][i][1], af[half_][i][2], af[half_][i][3],
                      stg + byt);
            }
#pragma unroll
            for (int jj = 0; jj < 8; jj += 2) {
                const uint32_t byt =
                    (uint32_t)(((warp_n + jj * 8 + brow_off) * ROW_H + kk + bcolr) * 2);
                LDMX4(bb[half_][jj][0], bb[half_][jj][1],
                      bb[half_][jj + 1][0], bb[half_][jj + 1][1],
                      stg + (uint32_t)(TILE_H * 2) + byt);
            }
        }

#pragma unroll
        for (int half_ = 0; half_ < 2; ++half_)
#pragma unroll
            for (int i = 0; i < 4; i++)
#pragma unroll
                for (int j = 0; j < 8; j++)
                    MMA16816(acc[i][j], af[half_][i], bb[half_][j]);
        // no trailing __syncthreads
    }
}

// ---------------------------------------------------------------------------
// Fused Q/K/V projection (1-pass): grid (8, 64, 3).
// ---------------------------------------------------------------------------
__global__ __launch_bounds__(128, 2)
void gemm_qkv(const half* __restrict__ x16, const half* __restrict__ ce16,
              const half* __restrict__ Wq16, const half* __restrict__ Wk16,
              const half* __restrict__ Wv16,
              const float* __restrict__ bq, const float* __restrict__ bk,
              const float* __restrict__ bv,
              half* __restrict__ Q16, half* __restrict__ K16,
              half* __restrict__ Vt16)
{
    extern __shared__ __align__(16) char smem_raw[];
    const int z  = blockIdx.z;
    const int m0 = blockIdx.y * 128;
    const int n0 = blockIdx.x * 128;

    const half *A_, *B_;
    const float* bias;
    if (z == 0)      { A_ = x16;  B_ = Wq16; bias = bq; }
    else if (z == 1) { A_ = ce16; B_ = Wk16; bias = bk; }
    else             { A_ = ce16; B_ = Wv16; bias = bv; }

    float acc[4][8][4];
#pragma unroll
    for (int i = 0; i < 4; i++)
#pragma unroll
        for (int j = 0; j < 8; j++)
#pragma unroll
            for (int c = 0; c < 4; c++) acc[i][j][c] = 0.f;

    gemm_core1(A_ + (size_t)m0 * C_DIM, B_ + (size_t)n0 * C_DIM,
               C_DIM, C_DIM, C_DIM, smem_raw, acc);

    const int tid  = threadIdx.x;
    const int wid  = tid >> 5;
    const int lane = tid & 31;
    const int warp_m = (wid & 1) * 64;
    const int warp_n = (wid >> 1) * 64;
    const int gq = lane >> 2;
    const int tq = lane & 3;

#pragma unroll
    for (int i = 0; i < 4; i++) {
#pragma unroll
        for (int j = 0; j < 8; j++) {
            const int col = n0 + warp_n + j * 8 + tq * 2;
#pragma unroll
            for (int h = 0; h < 2; h++) {
                const int row = m0 + warp_m + i * 16 + gq + h * 8;
                float2 bb = *reinterpret_cast<const float2*>(bias + col);
                float v0 = acc[i][j][2 * h]     + bb.x;
                float v1 = acc[i][j][2 * h + 1] + bb.y;
                if (z == 0) {
                    *reinterpret_cast<uint32_t*>(Q16 + (size_t)row * C_DIM + col) =
                        packh(__float2half(v0), __float2half(v1));
                } else if (z == 1) {
                    *reinterpret_cast<uint32_t*>(K16 + (size_t)row * C_DIM + col) =
                        packh(__float2half(v0), __float2half(v1));
                } else {
                    Vt16[(size_t)col * M_ALL + row]       = __float2half(v0);
                    Vt16[(size_t)(col + 1) * M_ALL + row] = __float2half(v1);
                }
            }
        }
    }
}

// ---------------------------------------------------------------------------
// 1-pass generic GEMM.
// OUT_MODE: 0 fp32 out (*alpha), 1 fp16 out (+residual), 2 fp32 out (+bias)
// ---------------------------------------------------------------------------
template<int OUT_MODE>
__global__ __launch_bounds__(128, 2)
void gemm1(const half* __restrict__ Ag, const half* __restrict__ Bg,
           const float* __restrict__ Rb,
           float* __restrict__ Cf, half* __restrict__ Ch,
           int K, float alpha, int ldA, int ldB, int ldC,
           long long sA, long long sB, long long sC, long long sR)
{
    extern __shared__ __align__(16) char smem_raw[];
    const int z  = blockIdx.z;
    const int m0 = blockIdx.y * 128;
    const int n0 = blockIdx.x * 128;

    float acc[4][8][4];
#pragma unroll
    for (int i = 0; i < 4; i++)
#pragma unroll
        for (int j = 0; j < 8; j++)
#pragma unroll
            for (int c = 0; c < 4; c++) acc[i][j][c] = 0.f;

    gemm_core1(Ag + z * sA + (size_t)m0 * ldA, Bg + z * sB + (size_t)n0 * ldB,
               ldA, ldB, K, smem_raw, acc);

    const int tid  = threadIdx.x;
    const int wid  = tid >> 5;
    const int lane = tid & 31;
    const int warp_m = (wid & 1) * 64;
    const int warp_n = (wid >> 1) * 64;
    const int gq = lane >> 2;
    const int tq = lane & 3;

#pragma unroll
    for (int i = 0; i < 4; i++) {
#pragma unroll
        for (int j = 0; j < 8; j++) {
            const int col = n0 + warp_n + j * 8 + tq * 2;
#pragma unroll
            for (int h = 0; h < 2; h++) {
                const int row = m0 + warp_m + i * 16 + gq + h * 8;
                float v0 = acc[i][j][2 * h];
                float v1 = acc[i][j][2 * h + 1];
                if (OUT_MODE == 0) {
                    *reinterpret_cast<float2*>(Cf + z * sC + (size_t)row * ldC + col)
                        = make_float2(v0 * alpha, v1 * alpha);
                } else if (OUT_MODE == 1) {
                    float2 r = *reinterpret_cast<const float2*>(
                        Rb + z * sR + (size_t)row * ldC + col);
                    *reinterpret_cast<uint32_t*>(Ch + z * sC + (size_t)row * ldC + col) =
                        packh(__float2half(v0 + r.x), __float2half(v1 + r.y));
                } else {
                    float2 bb = *reinterpret_cast<const float2*>(Rb + col);
                    *reinterpret_cast<float2*>(Cf + z * sC + (size_t)row * ldC + col)
                        = make_float2(v0 + bb.x, v1 + bb.y);
                }
            }
        }
    }
}

// ---------------------------------------------------------------------------
// Row softmax (2048/row) -> fp16 probabilities.
// ---------------------------------------------------------------------------
__global__ __launch_bounds__(256)
void softmax2048(const float* __restrict__ S, half* __restrict__ P)
{
    const long long row = blockIdx.x;
    const float* p = S + row * 2048;
    const int tid = threadIdx.x;
    const int w = tid >> 5, l = tid & 31;

    float v[8];
    {
        float4 x0 = *reinterpret_cast<const float4*>(p + tid * 8);
        float4 x1 = *reinterpret_cast<const float4*>(p + tid * 8 + 4);
        v[0] = x0.x; v[1] = x0.y; v[2] = x0.z; v[3] = x0.w;
        v[4] = x1.x; v[5] = x1.y; v[6] = x1.z; v[7] = x1.w;
    }
    __shared__ float smax[8], ssum[8];

    float m = v[0];
#pragma unroll
    for (int j = 1; j < 8; j++) m = fmaxf(m, v[j]);
#pragma unroll
    for (int off = 16; off >= 1; off >>= 1)
        m = fmaxf(m, __shfl_xor_sync(0xffffffffu, m, off));
    if (l == 0) smax[w] = m;
    __syncthreads();
    float bm = smax[0];
#pragma unroll
    for (int j = 1; j < 8; j++) bm = fmaxf(bm, smax[j]);

    float s = 0.f;
#pragma unroll
    for (int j = 0; j < 8; j++) { v[j] = expf(v[j] - bm); s += v[j]; }
#pragma unroll
    for (int off = 16; off >= 1; off >>= 1)
        s += __shfl_xor_sync(0xffffffffu, s, off);
    if (l == 0) ssum[w] = s;
    __syncthreads();
    float tot = ssum[0];
#pragma unroll
    for (int j = 1; j < 8; j++) tot += ssum[j];

    const float inv = 1.f / tot;
    half hh[8];
#pragma unroll
    for (int j = 0; j < 8; j++) hh[j] = __float2half(v[j] * inv);

    const long long ob = row * 2048 + tid * 8;
    *reinterpret_cast<uint2*>(P + ob) =
        make_uint2(packh(hh[0], hh[1]), packh(hh[2], hh[3]));
    *reinterpret_cast<uint2*>(P + ob + 4) =
        make_uint2(packh(hh[4], hh[5]), packh(hh[6], hh[7]));
}

// ---------------------------------------------------------------------------
extern "C" void kernel_launch(void* const* d_in, const int* in_sizes, int n_in,
                              void* d_out, int out_size)
{
    (void)in_sizes; (void)n_in; (void)out_size;
    const float* x  = (const float*)d_in[0];
    const float* ce = (const float*)d_in[1];
    const float* Wq = (const float*)d_in[2];
    const float* bq = (const float*)d_in[3];
    const float* Wk = (const float*)d_in[4];
    const float* bk = (const float*)d_in[5];
    const float* Wv = (const float*)d_in[6];
    const float* bv = (const float*)d_in[7];
    const float* Wo = (const float*)d_in[8];
    const float* bo = (const float*)d_in[9];
    float* out = (float*)d_out;

    float* S;
    half *x16, *ce16, *Wq16, *Wk16, *Wv16, *Wo16;
    half *Q16, *K16, *Vt16, *P16, *T16;
    cudaGetSymbolAddress((void**)&S,    g_S);
    cudaGetSymbolAddress((void**)&x16,  g_x16);  cudaGetSymbolAddress((void**)&ce16, g_ce16);
    cudaGetSymbolAddress((void**)&Wq16, g_Wq16); cudaGetSymbolAddress((void**)&Wk16, g_Wk16);
    cudaGetSymbolAddress((void**)&Wv16, g_Wv16); cudaGetSymbolAddress((void**)&Wo16, g_Wo16);
    cudaGetSymbolAddress((void**)&Q16,  g_Q16);  cudaGetSymbolAddress((void**)&K16,  g_K16);
    cudaGetSymbolAddress((void**)&Vt16, g_Vt16); cudaGetSymbolAddress((void**)&P16,  g_P16);
    cudaGetSymbolAddress((void**)&T16,  g_T16);

    cudaFuncSetAttribute(gemm_qkv, cudaFuncAttributeMaxDynamicSharedMemorySize, SMEM1);
    cudaFuncSetAttribute(gemm1<0>, cudaFuncAttributeMaxDynamicSharedMemorySize, SMEM1);
    cudaFuncSetAttribute(gemm1<1>, cudaFuncAttributeMaxDynamicSharedMemorySize, SMEM1);
    cudaFuncSetAttribute(gemm1<2>, cudaFuncAttributeMaxDynamicSharedMemorySize, SMEM1);

    round_all<<<20480, 256>>>(
        (const float4*)x, (const float4*)ce, (const float4*)Wq,
        (const float4*)Wk, (const float4*)Wv, (const float4*)Wo,
        (uint2*)x16, (uint2*)ce16, (uint2*)Wq16, (uint2*)Wk16,
        (uint2*)Wv16, (uint2*)Wo16);

    const long long sQ = (long long)S_DIM * C_DIM;
    const long long sS = (long long)S_DIM * S_DIM;

    // fused Q/K/V projections (1536 CTAs, 1-pass)
    gemm_qkv<<<dim3(8, 64, 3), 128, SMEM1>>>(
        x16, ce16, Wq16, Wk16, Wv16, bq, bk, bv, Q16, K16, Vt16);

    // scores: per-batch Q @ K^T / 32 -> fp32 S
    gemm1<0><<<dim3(16, 16, B_DIM), 128, SMEM1>>>(
        Q16, K16, nullptr, S, nullptr,
        C_DIM, 0.03125f, C_DIM, C_DIM, S_DIM, sQ, sQ, sS, 0);

    softmax2048<<<M_ALL, 256>>>(S, P16);

    // attended + residual -> fp16 T (single plane)
    gemm1<1><<<dim3(8, 16, B_DIM), 128, SMEM1>>>(
        P16, Vt16, x, nullptr, T16,
        S_DIM, 1.f, S_DIM, M_ALL, C_DIM, sS, S_DIM, sQ, sQ);

    // output projection (1-pass, fp32 out)
    gemm1<2><<<dim3(8, 64, 1), 128, SMEM1>>>(
        T16, Wo16, bo, out, nullptr,
        C_DIM, 1.f, C_DIM, C_DIM, C_DIM, 0, 0, (long long)S_DIM * C_DIM, 0);
}

// round 16
// speedup vs baseline: 1.6420x; 1.0384x over previous
#include <cuda_runtime.h>
#include <cuda_fp16.h>
#include <cstdint>
#include <math.h>

// ---------------------------------------------------------------------------
// SpatialTransformer via mma.sync fp16 (HMMA).
// Round 16: KT=64 ktiles (16 iters), 3-stage cp.async ring at distance 1,
// single __syncthreads per ktile. Same math as rounds 14/15.
// ---------------------------------------------------------------------------

#define B_DIM 4
#define S_DIM 2048
#define C_DIM 1024
#define M_ALL (B_DIM * S_DIM)   // 8192

__device__ float g_S[(long long)B_DIM * S_DIM * S_DIM];  // scores, 64 MB
__device__ half g_x16[M_ALL * C_DIM], g_ce16[M_ALL * C_DIM];
__device__ half g_Wq16[C_DIM * C_DIM], g_Wk16[C_DIM * C_DIM];
__device__ half g_Wv16[C_DIM * C_DIM], g_Wo16[C_DIM * C_DIM];
__device__ half g_Q16[M_ALL * C_DIM], g_K16[M_ALL * C_DIM];
__device__ half g_Vt16[C_DIM * M_ALL];                      // V^T [C][B*S]
__device__ half g_P16[(long long)B_DIM * S_DIM * S_DIM];
__device__ half g_T16[M_ALL * C_DIM];                       // x + attended (fp16)

__device__ __forceinline__ uint32_t smem_u32(const void* p) {
    uint32_t a;
    asm("{ .reg .u64 t; cvta.to.shared.u64 t, %1; cvt.u32.u64 %0, t; }"
        : "=r"(a) : "l"(p));
    return a;
}

#define LDMX4(r0, r1, r2, r3, addr) \
    asm volatile("ldmatrix.sync.aligned.m8n8.x4.shared.b16 {%0,%1,%2,%3}, [%4];" \
                 : "=r"(r0), "=r"(r1), "=r"(r2), "=r"(r3) : "r"(addr))
#define MMA16816(d, a, b) \
    asm volatile("mma.sync.aligned.m16n8k16.row.col.f32.f16.f16.f32 " \
                 "{%0,%1,%2,%3}, {%4,%5,%6,%7}, {%8,%9}, {%0,%1,%2,%3};" \
                 : "+f"((d)[0]), "+f"((d)[1]), "+f"((d)[2]), "+f"((d)[3]) \
                 : "r"((a)[0]), "r"((a)[1]), "r"((a)[2]), "r"((a)[3]), \
                   "r"((b)[0]), "r"((b)[1]))
#define CP_ASYNC16(dst, src) \
    asm volatile("cp.async.cg.shared.global [%0], [%1], 16;" \
                 :: "r"(dst), "l"(src) : "memory")
#define CP_COMMIT() asm volatile("cp.async.commit_group;" ::: "memory")

#define KT        64
#define ROW_H     72                      // 64 data halves + 8 pad
#define TILE_H    (128 * ROW_H)           // 9216 halves (18432 B)
#define STAGE1_H  (2 * TILE_H)            // A + B tile per stage (36864 B)
#define NSTAGE    3
#define SMEM1     (NSTAGE * STAGE1_H * 2) // 110592 B  (x2 CTAs = 221184)

__device__ __forceinline__ uint32_t packh(half a, half b) {
    __half2 t; t.x = a; t.y = b;
    return *reinterpret_cast<uint32_t*>(&t);
}

// ---------------------------------------------------------------------------
// Fused rounding pass: all six fp32 tensors -> fp16.
// ---------------------------------------------------------------------------
__global__ __launch_bounds__(256)
void round_all(const float4* __restrict__ x,  const float4* __restrict__ ce,
               const float4* __restrict__ Wq, const float4* __restrict__ Wk,
               const float4* __restrict__ Wv, const float4* __restrict__ Wo,
               uint2* __restrict__ x16,  uint2* __restrict__ ce16,
               uint2* __restrict__ Wq16, uint2* __restrict__ Wk16,
               uint2* __restrict__ Wv16, uint2* __restrict__ Wo16)
{
    const int b = blockIdx.x;
    const float4* in; uint2* o; int lb;
    if (b < 8192)       { in = x;  o = x16;  lb = b; }
    else if (b < 16384) { in = ce; o = ce16; lb = b - 8192; }
    else if (b < 17408) { in = Wq; o = Wq16; lb = b - 16384; }
    else if (b < 18432) { in = Wk; o = Wk16; lb = b - 17408; }
    else if (b < 19456) { in = Wv; o = Wv16; lb = b - 18432; }
    else                { in = Wo; o = Wo16; lb = b - 19456; }

    const int i = lb * 256 + threadIdx.x;
    float4 v = in[i];
    o[i] = make_uint2(packh(__float2half(v.x), __float2half(v.y)),
                      packh(__float2half(v.z), __float2half(v.w)));
}

// ---------------------------------------------------------------------------
// 1-pass mainloop: acc += A@B^T. KT=64, 3-stage ring, distance-1 prefetch,
// ONE __syncthreads per ktile.
// ---------------------------------------------------------------------------
__device__ __forceinline__ void gemm_core1(
    const half* __restrict__ Ag, const half* __restrict__ Bg,
    int ldA, int ldB, int K, char* smem_raw, float acc[4][8][4])
{
    const uint32_t sm_base = smem_u32(smem_raw);
    const int tid  = threadIdx.x;
    const int lane = tid & 31;
    const int wid  = tid >> 5;

    const int warp_m = (wid & 1) * 64;
    const int warp_n = (wid >> 1) * 64;

    // cp.async mapping: per tile 128 rows x 8 chunks(16B); 8 chunks/thread/tile
    const int r0 = tid >> 3;           // 0..15
    const int kc = (tid & 7) * 8;      // half offset 0..56

    const int arow  = warp_m + (lane & 15);
    const int acolr = (lane >> 4) << 3;
    const int brow_off = ((lane >> 4) << 3) + (lane & 7);
    const int bcolr = lane & 8;

    const int NK = K >> 6;

    auto load_stage = [&](int buf, int kt) {
        const uint32_t sbase = sm_base + (uint32_t)(buf * STAGE1_H) * 2;
        const int kk = kt * KT + kc;
#pragma unroll
        for (int rr = 0; rr < 8; rr++) {
            const int row = r0 + rr * 16;
            const uint32_t so = (uint32_t)(row * ROW_H + kc) * 2;
            CP_ASYNC16(sbase + so,                          Ag + (size_t)row * ldA + kk);
            CP_ASYNC16(sbase + (uint32_t)(TILE_H * 2) + so, Bg + (size_t)row * ldB + kk);
        }
    };

    load_stage(0, 0);
    CP_COMMIT();

    int stage = 0;       // stage of ktile kt
    for (int kt = 0; kt < NK; ++kt) {
        const int nstage = (stage == 2) ? 0 : stage + 1;
        if (kt + 1 < NK) {
            load_stage(nstage, kt + 1);
            CP_COMMIT();
            asm volatile("cp.async.wait_group 1;" ::: "memory");
        } else {
            asm volatile("cp.async.wait_group 0;" ::: "memory");
        }
        __syncthreads();   // single barrier per ktile

        const uint32_t stg = sm_base + (uint32_t)(stage * STAGE1_H) * 2;

        // two k32 pairs; fragments batched per pair (regs bounded)
#pragma unroll
        for (int pair = 0; pair < 2; ++pair) {
            uint32_t af[2][4][4];
            uint32_t bb[2][8][2];
#pragma unroll
            for (int half_ = 0; half_ < 2; ++half_) {
                const int kk = pair * 32 + half_ * 16;
#pragma unroll
                for (int i = 0; i < 4; i++) {
                    const uint32_t byt =
                        (uint32_t)(((arow + i * 16) * ROW_H + kk + acolr) * 2);
                    LDMX4(af[half_][i][0], af[half_][i][1],
                          af[half_][i][2], af[half_][i][3], stg + byt);
                }
#pragma unroll
                for (int jj = 0; jj < 8; jj += 2) {
                    const uint32_t byt =
                        (uint32_t)(((warp_n + jj * 8 + brow_off) * ROW_H + kk + bcolr) * 2);
                    LDMX4(bb[half_][jj][0], bb[half_][jj][1],
                          bb[half_][jj + 1][0], bb[half_][jj + 1][1],
                          stg + (uint32_t)(TILE_H * 2) + byt);
                }
            }
#pragma unroll
            for (int half_ = 0; half_ < 2; ++half_)
#pragma unroll
                for (int i = 0; i < 4; i++)
#pragma unroll
                    for (int j = 0; j < 8; j++)
                        MMA16816(acc[i][j], af[half_][i], bb[half_][j]);
        }
        stage = nstage;
        // no trailing barrier (writer targets stage+1; readers only current)
    }
}

// ---------------------------------------------------------------------------
// Fused Q/K/V projection (1-pass): grid (8, 64, 3).
// ---------------------------------------------------------------------------
__global__ __launch_bounds__(128, 2)
void gemm_qkv(const half* __restrict__ x16, const half* __restrict__ ce16,
              const half* __restrict__ Wq16, const half* __restrict__ Wk16,
              const half* __restrict__ Wv16,
              const float* __restrict__ bq, const float* __restrict__ bk,
              const float* __restrict__ bv,
              half* __restrict__ Q16, half* __restrict__ K16,
              half* __restrict__ Vt16)
{
    extern __shared__ __align__(16) char smem_raw[];
    const int z  = blockIdx.z;
    const int m0 = blockIdx.y * 128;
    const int n0 = blockIdx.x * 128;

    const half *A_, *B_;
    const float* bias;
    if (z == 0)      { A_ = x16;  B_ = Wq16; bias = bq; }
    else if (z == 1) { A_ = ce16; B_ = Wk16; bias = bk; }
    else             { A_ = ce16; B_ = Wv16; bias = bv; }

    float acc[4][8][4];
#pragma unroll
    for (int i = 0; i < 4; i++)
#pragma unroll
        for (int j = 0; j < 8; j++)
#pragma unroll
            for (int c = 0; c < 4; c++) acc[i][j][c] = 0.f;

    gemm_core1(A_ + (size_t)m0 * C_DIM, B_ + (size_t)n0 * C_DIM,
               C_DIM, C_DIM, C_DIM, smem_raw, acc);

    const int tid  = threadIdx.x;
    const int wid  = tid >> 5;
    const int lane = tid & 31;
    const int warp_m = (wid & 1) * 64;
    const int warp_n = (wid >> 1) * 64;
    const int gq = lane >> 2;
    const int tq = lane & 3;

#pragma unroll
    for (int i = 0; i < 4; i++) {
#pragma unroll
        for (int j = 0; j < 8; j++) {
            const int col = n0 + warp_n + j * 8 + tq * 2;
#pragma unroll
            for (int h = 0; h < 2; h++) {
                const int row = m0 + warp_m + i * 16 + gq + h * 8;
                float2 bb = *reinterpret_cast<const float2*>(bias + col);
                float v0 = acc[i][j][2 * h]     + bb.x;
                float v1 = acc[i][j][2 * h + 1] + bb.y;
                if (z == 0) {
                    *reinterpret_cast<uint32_t*>(Q16 + (size_t)row * C_DIM + col) =
                        packh(__float2half(v0), __float2half(v1));
                } else if (z == 1) {
                    *reinterpret_cast<uint32_t*>(K16 + (size_t)row * C_DIM + col) =
                        packh(__float2half(v0), __float2half(v1));
                } else {
                    Vt16[(size_t)col * M_ALL + row]       = __float2half(v0);
                    Vt16[(size_t)(col + 1) * M_ALL + row] = __float2half(v1);
                }
            }
        }
    }
}

// ---------------------------------------------------------------------------
// 1-pass generic GEMM.
// OUT_MODE: 0 fp32 out (*alpha), 1 fp16 out (+residual), 2 fp32 out (+bias)
// ---------------------------------------------------------------------------
template<int OUT_MODE>
__global__ __launch_bounds__(128, 2)
void gemm1(const half* __restrict__ Ag, const half* __restrict__ Bg,
           const float* __restrict__ Rb,
           float* __restrict__ Cf, half* __restrict__ Ch,
           int K, float alpha, int ldA, int ldB, int ldC,
           long long sA, long long sB, long long sC, long long sR)
{
    extern __shared__ __align__(16) char smem_raw[];
    const int z  = blockIdx.z;
    const int m0 = blockIdx.y * 128;
    const int n0 = blockIdx.x * 128;

    float acc[4][8][4];
#pragma unroll
    for (int i = 0; i < 4; i++)
#pragma unroll
        for (int j = 0; j < 8; j++)
#pragma unroll
            for (int c = 0; c < 4; c++) acc[i][j][c] = 0.f;

    gemm_core1(Ag + z * sA + (size_t)m0 * ldA, Bg + z * sB + (size_t)n0 * ldB,
               ldA, ldB, K, smem_raw, acc);

    const int tid  = threadIdx.x;
    const int wid  = tid >> 5;
    const int lane = tid & 31;
    const int warp_m = (wid & 1) * 64;
    const int warp_n = (wid >> 1) * 64;
    const int gq = lane >> 2;
    const int tq = lane & 3;

#pragma unroll
    for (int i = 0; i < 4; i++) {
#pragma unroll
        for (int j = 0; j < 8; j++) {
            const int col = n0 + warp_n + j * 8 + tq * 2;
#pragma unroll
            for (int h = 0; h < 2; h++) {
                const int row = m0 + warp_m + i * 16 + gq + h * 8;
                float v0 = acc[i][j][2 * h];
                float v1 = acc[i][j][2 * h + 1];
                if (OUT_MODE == 0) {
                    *reinterpret_cast<float2*>(Cf + z * sC + (size_t)row * ldC + col)
                        = make_float2(v0 * alpha, v1 * alpha);
                } else if (OUT_MODE == 1) {
                    float2 r = *reinterpret_cast<const float2*>(
                        Rb + z * sR + (size_t)row * ldC + col);
                    *reinterpret_cast<uint32_t*>(Ch + z * sC + (size_t)row * ldC + col) =
                        packh(__float2half(v0 + r.x), __float2half(v1 + r.y));
                } else {
                    float2 bb = *reinterpret_cast<const float2*>(Rb + col);
                    *reinterpret_cast<float2*>(Cf + z * sC + (size_t)row * ldC + col)
                        = make_float2(v0 + bb.x, v1 + bb.y);
                }
            }
        }
    }
}

// ---------------------------------------------------------------------------
// Row softmax (2048/row) -> fp16 probabilities.
// ---------------------------------------------------------------------------
__global__ __launch_bounds__(256)
void softmax2048(const float* __restrict__ S, half* __restrict__ P)
{
    const long long row = blockIdx.x;
    const float* p = S + row * 2048;
    const int tid = threadIdx.x;
    const int w = tid >> 5, l = tid & 31;

    float v[8];
    {
        float4 x0 = *reinterpret_cast<const float4*>(p + tid * 8);
        float4 x1 = *reinterpret_cast<const float4*>(p + tid * 8 + 4);
        v[0] = x0.x; v[1] = x0.y; v[2] = x0.z; v[3] = x0.w;
        v[4] = x1.x; v[5] = x1.y; v[6] = x1.z; v[7] = x1.w;
    }
    __shared__ float smax[8], ssum[8];

    float m = v[0];
#pragma unroll
    for (int j = 1; j < 8; j++) m = fmaxf(m, v[j]);
#pragma unroll
    for (int off = 16; off >= 1; off >>= 1)
        m = fmaxf(m, __shfl_xor_sync(0xffffffffu, m, off));
    if (l == 0) smax[w] = m;
    __syncthreads();
    float bm = smax[0];
#pragma unroll
    for (int j = 1; j < 8; j++) bm = fmaxf(bm, smax[j]);

    float s = 0.f;
#pragma unroll
    for (int j = 0; j < 8; j++) { v[j] = expf(v[j] - bm); s += v[j]; }
#pragma unroll
    for (int off = 16; off >= 1; off >>= 1)
        s += __shfl_xor_sync(0xffffffffu, s, off);
    if (l == 0) ssum[w] = s;
    __syncthreads();
    float tot = ssum[0];
#pragma unroll
    for (int j = 1; j < 8; j++) tot += ssum[j];

    const float inv = 1.f / tot;
    half hh[8];
#pragma unroll
    for (int j = 0; j < 8; j++) hh[j] = __float2half(v[j] * inv);

    const long long ob = row * 2048 + tid * 8;
    *reinterpret_cast<uint2*>(P + ob) =
        make_uint2(packh(hh[0], hh[1]), packh(hh[2], hh[3]));
    *reinterpret_cast<uint2*>(P + ob + 4) =
        make_uint2(packh(hh[4], hh[5]), packh(hh[6], hh[7]));
}

// ---------------------------------------------------------------------------
extern "C" void kernel_launch(void* const* d_in, const int* in_sizes, int n_in,
                              void* d_out, int out_size)
{
    (void)in_sizes; (void)n_in; (void)out_size;
    const float* x  = (const float*)d_in[0];
    const float* ce = (const float*)d_in[1];
    const float* Wq = (const float*)d_in[2];
    const float* bq = (const float*)d_in[3];
    const float* Wk = (const float*)d_in[4];
    const float* bk = (const float*)d_in[5];
    const float* Wv = (const float*)d_in[6];
    const float* bv = (const float*)d_in[7];
    const float* Wo = (const float*)d_in[8];
    const float* bo = (const float*)d_in[9];
    float* out = (float*)d_out;

    float* S;
    half *x16, *ce16, *Wq16, *Wk16, *Wv16, *Wo16;
    half *Q16, *K16, *Vt16, *P16, *T16;
    cudaGetSymbolAddress((void**)&S,    g_S);
    cudaGetSymbolAddress((void**)&x16,  g_x16);  cudaGetSymbolAddress((void**)&ce16, g_ce16);
    cudaGetSymbolAddress((void**)&Wq16, g_Wq16); cudaGetSymbolAddress((void**)&Wk16, g_Wk16);
    cudaGetSymbolAddress((void**)&Wv16, g_Wv16); cudaGetSymbolAddress((void**)&Wo16, g_Wo16);
    cudaGetSymbolAddress((void**)&Q16,  g_Q16);  cudaGetSymbolAddress((void**)&K16,  g_K16);
    cudaGetSymbolAddress((void**)&Vt16, g_Vt16); cudaGetSymbolAddress((void**)&P16,  g_P16);
    cudaGetSymbolAddress((void**)&T16,  g_T16);

    cudaFuncSetAttribute(gemm_qkv, cudaFuncAttributeMaxDynamicSharedMemorySize, SMEM1);
    cudaFuncSetAttribute(gemm1<0>, cudaFuncAttributeMaxDynamicSharedMemorySize, SMEM1);
    cudaFuncSetAttribute(gemm1<1>, cudaFuncAttributeMaxDynamicSharedMemorySize, SMEM1);
    cudaFuncSetAttribute(gemm1<2>, cudaFuncAttributeMaxDynamicSharedMemorySize, SMEM1);

    round_all<<<20480, 256>>>(
        (const float4*)x, (const float4*)ce, (const float4*)Wq,
        (const float4*)Wk, (const float4*)Wv, (const float4*)Wo,
        (uint2*)x16, (uint2*)ce16, (uint2*)Wq16, (uint2*)Wk16,
        (uint2*)Wv16, (uint2*)Wo16);

    const long long sQ = (long long)S_DIM * C_DIM;
    const long long sS = (long long)S_DIM * S_DIM;

    // fused Q/K/V projections (1536 CTAs, 1-pass)
    gemm_qkv<<<dim3(8, 64, 3), 128, SMEM1>>>(
        x16, ce16, Wq16, Wk16, Wv16, bq, bk, bv, Q16, K16, Vt16);

    // scores: per-batch Q @ K^T / 32 -> fp32 S
    gemm1<0><<<dim3(16, 16, B_DIM), 128, SMEM1>>>(
        Q16, K16, nullptr, S, nullptr,
        C_DIM, 0.03125f, C_DIM, C_DIM, S_DIM, sQ, sQ, sS, 0);

    softmax2048<<<M_ALL, 256>>>(S, P16);

    // attended + residual -> fp16 T (single plane)
    gemm1<1><<<dim3(8, 16, B_DIM), 128, SMEM1>>>(
        P16, Vt16, x, nullptr, T16,
        S_DIM, 1.f, S_DIM, M_ALL, C_DIM, sS, S_DIM, sQ, sQ);

    // output projection (1-pass, fp32 out)
    gemm1<2><<<dim3(8, 64, 1), 128, SMEM1>>>(
        T16, Wo16, bo, out, nullptr,
        C_DIM, 1.f, C_DIM, C_DIM, C_DIM, 0, 0, (long long)S_DIM * C_DIM, 0);
}

// round 17
// speedup vs baseline: 1.6534x; 1.0070x over previous
#include <cuda_runtime.h>
#include <cuda_fp16.h>
#include <cstdint>
#include <math.h>

// ---------------------------------------------------------------------------
// SpatialTransformer via mma.sync fp16 (HMMA).
// Round 17: round-16 core (KT=64, 3-stage ring, single barrier/ktile);
// scores plane stored fp16 (halves scores-store + softmax-read traffic).
// ---------------------------------------------------------------------------

#define B_DIM 4
#define S_DIM 2048
#define C_DIM 1024
#define M_ALL (B_DIM * S_DIM)   // 8192

__device__ half g_S16[(long long)B_DIM * S_DIM * S_DIM]; // scores fp16, 32 MB
__device__ half g_x16[M_ALL * C_DIM], g_ce16[M_ALL * C_DIM];
__device__ half g_Wq16[C_DIM * C_DIM], g_Wk16[C_DIM * C_DIM];
__device__ half g_Wv16[C_DIM * C_DIM], g_Wo16[C_DIM * C_DIM];
__device__ half g_Q16[M_ALL * C_DIM], g_K16[M_ALL * C_DIM];
__device__ half g_Vt16[C_DIM * M_ALL];                      // V^T [C][B*S]
__device__ half g_P16[(long long)B_DIM * S_DIM * S_DIM];
__device__ half g_T16[M_ALL * C_DIM];                       // x + attended (fp16)

__device__ __forceinline__ uint32_t smem_u32(const void* p) {
    uint32_t a;
    asm("{ .reg .u64 t; cvta.to.shared.u64 t, %1; cvt.u32.u64 %0, t; }"
        : "=r"(a) : "l"(p));
    return a;
}

#define LDMX4(r0, r1, r2, r3, addr) \
    asm volatile("ldmatrix.sync.aligned.m8n8.x4.shared.b16 {%0,%1,%2,%3}, [%4];" \
                 : "=r"(r0), "=r"(r1), "=r"(r2), "=r"(r3) : "r"(addr))
#define MMA16816(d, a, b) \
    asm volatile("mma.sync.aligned.m16n8k16.row.col.f32.f16.f16.f32 " \
                 "{%0,%1,%2,%3}, {%4,%5,%6,%7}, {%8,%9}, {%0,%1,%2,%3};" \
                 : "+f"((d)[0]), "+f"((d)[1]), "+f"((d)[2]), "+f"((d)[3]) \
                 : "r"((a)[0]), "r"((a)[1]), "r"((a)[2]), "r"((a)[3]), \
                   "r"((b)[0]), "r"((b)[1]))
#define CP_ASYNC16(dst, src) \
    asm volatile("cp.async.cg.shared.global [%0], [%1], 16;" \
                 :: "r"(dst), "l"(src) : "memory")
#define CP_COMMIT() asm volatile("cp.async.commit_group;" ::: "memory")

#define KT        64
#define ROW_H     72                      // 64 data halves + 8 pad
#define TILE_H    (128 * ROW_H)           // 9216 halves (18432 B)
#define STAGE1_H  (2 * TILE_H)            // A + B tile per stage (36864 B)
#define NSTAGE    3
#define SMEM1     (NSTAGE * STAGE1_H * 2) // 110592 B  (x2 CTAs = 221184)

__device__ __forceinline__ uint32_t packh(half a, half b) {
    __half2 t; t.x = a; t.y = b;
    return *reinterpret_cast<uint32_t*>(&t);
}

// ---------------------------------------------------------------------------
// Fused rounding pass: all six fp32 tensors -> fp16.
// ---------------------------------------------------------------------------
__global__ __launch_bounds__(256)
void round_all(const float4* __restrict__ x,  const float4* __restrict__ ce,
               const float4* __restrict__ Wq, const float4* __restrict__ Wk,
               const float4* __restrict__ Wv, const float4* __restrict__ Wo,
               uint2* __restrict__ x16,  uint2* __restrict__ ce16,
               uint2* __restrict__ Wq16, uint2* __restrict__ Wk16,
               uint2* __restrict__ Wv16, uint2* __restrict__ Wo16)
{
    const int b = blockIdx.x;
    const float4* in; uint2* o; int lb;
    if (b < 8192)       { in = x;  o = x16;  lb = b; }
    else if (b < 16384) { in = ce; o = ce16; lb = b - 8192; }
    else if (b < 17408) { in = Wq; o = Wq16; lb = b - 16384; }
    else if (b < 18432) { in = Wk; o = Wk16; lb = b - 17408; }
    else if (b < 19456) { in = Wv; o = Wv16; lb = b - 18432; }
    else                { in = Wo; o = Wo16; lb = b - 19456; }

    const int i = lb * 256 + threadIdx.x;
    float4 v = in[i];
    o[i] = make_uint2(packh(__float2half(v.x), __float2half(v.y)),
                      packh(__float2half(v.z), __float2half(v.w)));
}

// ---------------------------------------------------------------------------
// 1-pass mainloop: acc += A@B^T. KT=64, 3-stage ring, distance-1 prefetch,
// ONE __syncthreads per ktile.
// ---------------------------------------------------------------------------
__device__ __forceinline__ void gemm_core1(
    const half* __restrict__ Ag, const half* __restrict__ Bg,
    int ldA, int ldB, int K, char* smem_raw, float acc[4][8][4])
{
    const uint32_t sm_base = smem_u32(smem_raw);
    const int tid  = threadIdx.x;
    const int lane = tid & 31;
    const int wid  = tid >> 5;

    const int warp_m = (wid & 1) * 64;
    const int warp_n = (wid >> 1) * 64;

    const int r0 = tid >> 3;           // 0..15
    const int kc = (tid & 7) * 8;      // half offset 0..56

    const int arow  = warp_m + (lane & 15);
    const int acolr = (lane >> 4) << 3;
    const int brow_off = ((lane >> 4) << 3) + (lane & 7);
    const int bcolr = lane & 8;

    const int NK = K >> 6;

    auto load_stage = [&](int buf, int kt) {
        const uint32_t sbase = sm_base + (uint32_t)(buf * STAGE1_H) * 2;
        const int kk = kt * KT + kc;
#pragma unroll
        for (int rr = 0; rr < 8; rr++) {
            const int row = r0 + rr * 16;
            const uint32_t so = (uint32_t)(row * ROW_H + kc) * 2;
            CP_ASYNC16(sbase + so,                          Ag + (size_t)row * ldA + kk);
            CP_ASYNC16(sbase + (uint32_t)(TILE_H * 2) + so, Bg + (size_t)row * ldB + kk);
        }
    };

    load_stage(0, 0);
    CP_COMMIT();

    int stage = 0;
    for (int kt = 0; kt < NK; ++kt) {
        const int nstage = (stage == 2) ? 0 : stage + 1;
        if (kt + 1 < NK) {
            load_stage(nstage, kt + 1);
            CP_COMMIT();
            asm volatile("cp.async.wait_group 1;" ::: "memory");
        } else {
            asm volatile("cp.async.wait_group 0;" ::: "memory");
        }
        __syncthreads();   // single barrier per ktile

        const uint32_t stg = sm_base + (uint32_t)(stage * STAGE1_H) * 2;

#pragma unroll
        for (int pair = 0; pair < 2; ++pair) {
            uint32_t af[2][4][4];
            uint32_t bb[2][8][2];
#pragma unroll
            for (int half_ = 0; half_ < 2; ++half_) {
                const int kk = pair * 32 + half_ * 16;
#pragma unroll
                for (int i = 0; i < 4; i++) {
                    const uint32_t byt =
                        (uint32_t)(((arow + i * 16) * ROW_H + kk + acolr) * 2);
                    LDMX4(af[half_][i][0], af[half_][i][1],
                          af[half_][i][2], af[half_][i][3], stg + byt);
                }
#pragma unroll
                for (int jj = 0; jj < 8; jj += 2) {
                    const uint32_t byt =
                        (uint32_t)(((warp_n + jj * 8 + brow_off) * ROW_H + kk + bcolr) * 2);
                    LDMX4(bb[half_][jj][0], bb[half_][jj][1],
                          bb[half_][jj + 1][0], bb[half_][jj + 1][1],
                          stg + (uint32_t)(TILE_H * 2) + byt);
                }
            }
#pragma unroll
            for (int half_ = 0; half_ < 2; ++half_)
#pragma unroll
                for (int i = 0; i < 4; i++)
#pragma unroll
                    for (int j = 0; j < 8; j++)
                        MMA16816(acc[i][j], af[half_][i], bb[half_][j]);
        }
        stage = nstage;
    }
}

// ---------------------------------------------------------------------------
// Fused Q/K/V projection (1-pass): grid (8, 64, 3).
// ---------------------------------------------------------------------------
__global__ __launch_bounds__(128, 2)
void gemm_qkv(const half* __restrict__ x16, const half* __restrict__ ce16,
              const half* __restrict__ Wq16, const half* __restrict__ Wk16,
              const half* __restrict__ Wv16,
              const float* __restrict__ bq, const float* __restrict__ bk,
              const float* __restrict__ bv,
              half* __restrict__ Q16, half* __restrict__ K16,
              half* __restrict__ Vt16)
{
    extern __shared__ __align__(16) char smem_raw[];
    const int z  = blockIdx.z;
    const int m0 = blockIdx.y * 128;
    const int n0 = blockIdx.x * 128;

    const half *A_, *B_;
    const float* bias;
    if (z == 0)      { A_ = x16;  B_ = Wq16; bias = bq; }
    else if (z == 1) { A_ = ce16; B_ = Wk16; bias = bk; }
    else             { A_ = ce16; B_ = Wv16; bias = bv; }

    float acc[4][8][4];
#pragma unroll
    for (int i = 0; i < 4; i++)
#pragma unroll
        for (int j = 0; j < 8; j++)
#pragma unroll
            for (int c = 0; c < 4; c++) acc[i][j][c] = 0.f;

    gemm_core1(A_ + (size_t)m0 * C_DIM, B_ + (size_t)n0 * C_DIM,
               C_DIM, C_DIM, C_DIM, smem_raw, acc);

    const int tid  = threadIdx.x;
    const int wid  = tid >> 5;
    const int lane = tid & 31;
    const int warp_m = (wid & 1) * 64;
    const int warp_n = (wid >> 1) * 64;
    const int gq = lane >> 2;
    const int tq = lane & 3;

#pragma unroll
    for (int i = 0; i < 4; i++) {
#pragma unroll
        for (int j = 0; j < 8; j++) {
            const int col = n0 + warp_n + j * 8 + tq * 2;
#pragma unroll
            for (int h = 0; h < 2; h++) {
                const int row = m0 + warp_m + i * 16 + gq + h * 8;
                float2 bb = *reinterpret_cast<const float2*>(bias + col);
                float v0 = acc[i][j][2 * h]     + bb.x;
                float v1 = acc[i][j][2 * h + 1] + bb.y;
                if (z == 0) {
                    *reinterpret_cast<uint32_t*>(Q16 + (size_t)row * C_DIM + col) =
                        packh(__float2half(v0), __float2half(v1));
                } else if (z == 1) {
                    *reinterpret_cast<uint32_t*>(K16 + (size_t)row * C_DIM + col) =
                        packh(__float2half(v0), __float2half(v1));
                } else {
                    Vt16[(size_t)col * M_ALL + row]       = __float2half(v0);
                    Vt16[(size_t)(col + 1) * M_ALL + row] = __float2half(v1);
                }
            }
        }
    }
}

// ---------------------------------------------------------------------------
// 1-pass generic GEMM.
// OUT_MODE: 0 fp16 out (*alpha)  [scores]
//           1 fp16 out (+fp32 residual) [attnV]
//           2 fp32 out (+bias)   [outproj]
// ---------------------------------------------------------------------------
template<int OUT_MODE>
__global__ __launch_bounds__(128, 2)
void gemm1(const half* __restrict__ Ag, const half* __restrict__ Bg,
           const float* __restrict__ Rb,
           float* __restrict__ Cf, half* __restrict__ Ch,
           int K, float alpha, int ldA, int ldB, int ldC,
           long long sA, long long sB, long long sC, long long sR)
{
    extern __shared__ __align__(16) char smem_raw[];
    const int z  = blockIdx.z;
    const int m0 = blockIdx.y * 128;
    const int n0 = blockIdx.x * 128;

    float acc[4][8][4];
#pragma unroll
    for (int i = 0; i < 4; i++)
#pragma unroll
        for (int j = 0; j < 8; j++)
#pragma unroll
            for (int c = 0; c < 4; c++) acc[i][j][c] = 0.f;

    gemm_core1(Ag + z * sA + (size_t)m0 * ldA, Bg + z * sB + (size_t)n0 * ldB,
               ldA, ldB, K, smem_raw, acc);

    const int tid  = threadIdx.x;
    const int wid  = tid >> 5;
    const int lane = tid & 31;
    const int warp_m = (wid & 1) * 64;
    const int warp_n = (wid >> 1) * 64;
    const int gq = lane >> 2;
    const int tq = lane & 3;

#pragma unroll
    for (int i = 0; i < 4; i++) {
#pragma unroll
        for (int j = 0; j < 8; j++) {
            const int col = n0 + warp_n + j * 8 + tq * 2;
#pragma unroll
            for (int h = 0; h < 2; h++) {
                const int row = m0 + warp_m + i * 16 + gq + h * 8;
                float v0 = acc[i][j][2 * h];
                float v1 = acc[i][j][2 * h + 1];
                if (OUT_MODE == 0) {
                    // scores: * alpha, fp16 out
                    *reinterpret_cast<uint32_t*>(Ch + z * sC + (size_t)row * ldC + col) =
                        packh(__float2half(v0 * alpha), __float2half(v1 * alpha));
                } else if (OUT_MODE == 1) {
                    float2 r = *reinterpret_cast<const float2*>(
                        Rb + z * sR + (size_t)row * ldC + col);
                    *reinterpret_cast<uint32_t*>(Ch + z * sC + (size_t)row * ldC + col) =
                        packh(__float2half(v0 + r.x), __float2half(v1 + r.y));
                } else {
                    float2 bb = *reinterpret_cast<const float2*>(Rb + col);
                    *reinterpret_cast<float2*>(Cf + z * sC + (size_t)row * ldC + col)
                        = make_float2(v0 + bb.x, v1 + bb.y);
                }
            }
        }
    }
}

// ---------------------------------------------------------------------------
// Row softmax (2048/row, fp16 in) -> fp16 probabilities.
// ---------------------------------------------------------------------------
__global__ __launch_bounds__(256)
void softmax2048(const half* __restrict__ S, half* __restrict__ P)
{
    const long long row = blockIdx.x;
    const half* p = S + row * 2048;
    const int tid = threadIdx.x;
    const int w = tid >> 5, l = tid & 31;

    float v[8];
    {
        uint4 raw = *reinterpret_cast<const uint4*>(p + tid * 8);
        const uint32_t u[4] = {raw.x, raw.y, raw.z, raw.w};
#pragma unroll
        for (int c = 0; c < 4; c++) {
            __half2 h2 = *reinterpret_cast<const __half2*>(&u[c]);
            float2 f2 = __half22float2(h2);
            v[c * 2]     = f2.x;
            v[c * 2 + 1] = f2.y;
        }
    }
    __shared__ float smax[8], ssum[8];

    float m = v[0];
#pragma unroll
    for (int j = 1; j < 8; j++) m = fmaxf(m, v[j]);
#pragma unroll
    for (int off = 16; off >= 1; off >>= 1)
        m = fmaxf(m, __shfl_xor_sync(0xffffffffu, m, off));
    if (l == 0) smax[w] = m;
    __syncthreads();
    float bm = smax[0];
#pragma unroll
    for (int j = 1; j < 8; j++) bm = fmaxf(bm, smax[j]);

    float s = 0.f;
#pragma unroll
    for (int j = 0; j < 8; j++) { v[j] = expf(v[j] - bm); s += v[j]; }
#pragma unroll
    for (int off = 16; off >= 1; off >>= 1)
        s += __shfl_xor_sync(0xffffffffu, s, off);
    if (l == 0) ssum[w] = s;
    __syncthreads();
    float tot = ssum[0];
#pragma unroll
    for (int j = 1; j < 8; j++) tot += ssum[j];

    const float inv = 1.f / tot;
    half hh[8];
#pragma unroll
    for (int j = 0; j < 8; j++) hh[j] = __float2half(v[j] * inv);

    const long long ob = row * 2048 + tid * 8;
    *reinterpret_cast<uint2*>(P + ob) =
        make_uint2(packh(hh[0], hh[1]), packh(hh[2], hh[3]));
    *reinterpret_cast<uint2*>(P + ob + 4) =
        make_uint2(packh(hh[4], hh[5]), packh(hh[6], hh[7]));
}

// ---------------------------------------------------------------------------
extern "C" void kernel_launch(void* const* d_in, const int* in_sizes, int n_in,
                              void* d_out, int out_size)
{
    (void)in_sizes; (void)n_in; (void)out_size;
    const float* x  = (const float*)d_in[0];
    const float* ce = (const float*)d_in[1];
    const float* Wq = (const float*)d_in[2];
    const float* bq = (const float*)d_in[3];
    const float* Wk = (const float*)d_in[4];
    const float* bk = (const float*)d_in[5];
    const float* Wv = (const float*)d_in[6];
    const float* bv = (const float*)d_in[7];
    const float* Wo = (const float*)d_in[8];
    const float* bo = (const float*)d_in[9];
    float* out = (float*)d_out;

    half *S16, *x16, *ce16, *Wq16, *Wk16, *Wv16, *Wo16;
    half *Q16, *K16, *Vt16, *P16, *T16;
    cudaGetSymbolAddress((void**)&S16,  g_S16);
    cudaGetSymbolAddress((void**)&x16,  g_x16);  cudaGetSymbolAddress((void**)&ce16, g_ce16);
    cudaGetSymbolAddress((void**)&Wq16, g_Wq16); cudaGetSymbolAddress((void**)&Wk16, g_Wk16);
    cudaGetSymbolAddress((void**)&Wv16, g_Wv16); cudaGetSymbolAddress((void**)&Wo16, g_Wo16);
    cudaGetSymbolAddress((void**)&Q16,  g_Q16);  cudaGetSymbolAddress((void**)&K16,  g_K16);
    cudaGetSymbolAddress((void**)&Vt16, g_Vt16); cudaGetSymbolAddress((void**)&P16,  g_P16);
    cudaGetSymbolAddress((void**)&T16,  g_T16);

    cudaFuncSetAttribute(gemm_qkv, cudaFuncAttributeMaxDynamicSharedMemorySize, SMEM1);
    cudaFuncSetAttribute(gemm1<0>, cudaFuncAttributeMaxDynamicSharedMemorySize, SMEM1);
    cudaFuncSetAttribute(gemm1<1>, cudaFuncAttributeMaxDynamicSharedMemorySize, SMEM1);
    cudaFuncSetAttribute(gemm1<2>, cudaFuncAttributeMaxDynamicSharedMemorySize, SMEM1);

    round_all<<<20480, 256>>>(
        (const float4*)x, (const float4*)ce, (const float4*)Wq,
        (const float4*)Wk, (const float4*)Wv, (const float4*)Wo,
        (uint2*)x16, (uint2*)ce16, (uint2*)Wq16, (uint2*)Wk16,
        (uint2*)Wv16, (uint2*)Wo16);

    const long long sQ = (long long)S_DIM * C_DIM;
    const long long sS = (long long)S_DIM * S_DIM;

    // fused Q/K/V projections (1536 CTAs, 1-pass)
    gemm_qkv<<<dim3(8, 64, 3), 128, SMEM1>>>(
        x16, ce16, Wq16, Wk16, Wv16, bq, bk, bv, Q16, K16, Vt16);

    // scores: per-batch Q @ K^T / 32 -> fp16 S
    gemm1<0><<<dim3(16, 16, B_DIM), 128, SMEM1>>>(
        Q16, K16, nullptr, nullptr, S16,
        C_DIM, 0.03125f, C_DIM, C_DIM, S_DIM, sQ, sQ, sS, 0);

    softmax2048<<<M_ALL, 256>>>(S16, P16);

    // attended + residual -> fp16 T
    gemm1<1><<<dim3(8, 16, B_DIM), 128, SMEM1>>>(
        P16, Vt16, x, nullptr, T16,
        S_DIM, 1.f, S_DIM, M_ALL, C_DIM, sS, S_DIM, sQ, sQ);

    // output projection (1-pass, fp32 out)
    gemm1<2><<<dim3(8, 64, 1), 128, SMEM1>>>(
        T16, Wo16, bo, out, nullptr,
        C_DIM, 1.f, C_DIM, C_DIM, C_DIM, 0, 0, (long long)S_DIM * C_DIM, 0);
}